// round 3
// baseline (speedup 1.0000x reference)
#include <cuda_runtime.h>
#include <math.h>

#define TT 200
#define BB 64
#define SS 8
#define DD 128
#define RR 512
#define ZZ 256
#define HH 1024
#define BSZ (BB*SS)            /* 512 rows per step */
#define DT_C 0.05f
#define SQRT_DT_C 0.223606797749979f
#define LOG2PI_C 1.8378770664093453f

#define KLD_PARTS  (1600*4)
#define RECON_PARTS (1600*2)

// ---------------- device scratch (static, allocation-free) ----------------
__device__ float g_hprior[TT*BB*HH];        // h@drift_w1[:R] + b1
__device__ float g_hpost [TT*BB*HH];        // hpos@drift_w1[:R] + b1
__device__ float g_ppart [TT*BB*HH];        // h@p_w1[:R] + p_b1
__device__ float g_dtmp  [TT*BB*HH];        // relu(h@diff_w1+b1)
__device__ float g_diff  [TT*BB*ZZ];        // exp(diff MLP)
__device__ float g_Mt    [TT*BB];
__device__ float g_states[(TT+1)*BSZ*ZZ];   // z trajectory
__device__ float g_zw    [TT*BSZ*HH];       // z_t @ drift_w1[R:]
__device__ float g_post  [TT*BSZ*ZZ];       // posterior drift
__device__ float g_A3    [TT*BSZ*HH];       // decoder hidden
__device__ float g_kld_part[KLD_PARTS];
__device__ float g_recon_part[RECON_PARTS];

// ---------------- generic 64x64 fp32 GEMM with fused pro/epilogues --------
#define PRO_PLAIN 0
#define PRO_ADDRELU 1      // A := relu(A + aux[(m>>3)*H + k])
#define EPI_STORE 0        // C = acc (+bias)
#define EPI_RELU  1
#define EPI_EXP   2
#define EPI_BCASTRELU 3    // C = relu(acc + aux[(m>>3)*H + n])
#define EPI_KLD   4        // reduce ((0.1 tanh(acc+b)-post)/diff)^2
#define EPI_RECON 5        // reduce 0.5(log2pi+(X-(acc+b))^2)*Mt

template<int PRO, int EPI>
__global__ void __launch_bounds__(256) gemm_k(
    const float* __restrict__ A, int lda,
    const float* __restrict__ Bm, int ldb,
    float* __restrict__ C, int ldc, int K,
    const float* __restrict__ bias,
    const float* __restrict__ aux,
    const float* __restrict__ aux2,
    const float* __restrict__ aux3,
    float* __restrict__ part)
{
    __shared__ float As[16][64];
    __shared__ float Bs[16][64];
    const int tid = threadIdx.x;
    const int tx = tid & 15, ty = tid >> 4;
    const int m0 = blockIdx.y * 64, n0 = blockIdx.x * 64;
    const int arow = tid >> 2;            // 0..63
    const int ak4  = (tid & 3) << 2;      // 0,4,8,12
    const int brow = tid >> 4;            // 0..15
    const int bn4  = (tid & 15) << 2;

    float acc[4][4];
#pragma unroll
    for (int i = 0; i < 4; i++)
#pragma unroll
        for (int j = 0; j < 4; j++) acc[i][j] = 0.f;

    for (int k0 = 0; k0 < K; k0 += 16) {
        float4 av = *(const float4*)&A[(size_t)(m0 + arow) * lda + k0 + ak4];
        if (PRO == PRO_ADDRELU) {
            const float4 hv = *(const float4*)&aux[(size_t)((m0 + arow) >> 3) * HH + k0 + ak4];
            av.x = fmaxf(av.x + hv.x, 0.f); av.y = fmaxf(av.y + hv.y, 0.f);
            av.z = fmaxf(av.z + hv.z, 0.f); av.w = fmaxf(av.w + hv.w, 0.f);
        }
        As[ak4 + 0][arow] = av.x; As[ak4 + 1][arow] = av.y;
        As[ak4 + 2][arow] = av.z; As[ak4 + 3][arow] = av.w;
        *(float4*)&Bs[brow][bn4] =
            *(const float4*)&Bm[(size_t)(k0 + brow) * ldb + n0 + bn4];
        __syncthreads();
#pragma unroll
        for (int kk = 0; kk < 16; kk++) {
            float4 a = *(float4*)&As[kk][ty * 4];
            float4 b = *(float4*)&Bs[kk][tx * 4];
            acc[0][0] += a.x * b.x; acc[0][1] += a.x * b.y; acc[0][2] += a.x * b.z; acc[0][3] += a.x * b.w;
            acc[1][0] += a.y * b.x; acc[1][1] += a.y * b.y; acc[1][2] += a.y * b.z; acc[1][3] += a.y * b.w;
            acc[2][0] += a.z * b.x; acc[2][1] += a.z * b.y; acc[2][2] += a.z * b.z; acc[2][3] += a.z * b.w;
            acc[3][0] += a.w * b.x; acc[3][1] += a.w * b.y; acc[3][2] += a.w * b.z; acc[3][3] += a.w * b.w;
        }
        __syncthreads();
    }

    if (EPI <= 3) {
        const bool hasb = (bias != nullptr);
#pragma unroll
        for (int i = 0; i < 4; i++) {
            const int m = m0 + ty * 4 + i;
#pragma unroll
            for (int j = 0; j < 4; j++) {
                const int n = n0 + tx * 4 + j;
                float v = acc[i][j];
                if (hasb) v += bias[n];
                if (EPI == EPI_RELU) v = fmaxf(v, 0.f);
                if (EPI == EPI_EXP)  v = expf(v);
                if (EPI == EPI_BCASTRELU)
                    v = fmaxf(v + aux[(size_t)(m >> 3) * HH + n], 0.f);
                C[(size_t)m * ldc + n] = v;
            }
        }
    } else {
        float s = 0.f;
#pragma unroll
        for (int i = 0; i < 4; i++) {
            const int m = m0 + ty * 4 + i;
#pragma unroll
            for (int j = 0; j < 4; j++) {
                const int n = n0 + tx * 4 + j;
                float v = acc[i][j] + bias[n];
                if (EPI == EPI_KLD) {
                    float pr = 0.1f * tanhf(v);
                    float e = (pr - aux2[(size_t)m * ZZ + n]) /
                              aux3[(size_t)(m >> 3) * ZZ + n];
                    s += e * e;
                } else { // EPI_RECON
                    float d = aux[(size_t)(m >> 3) * DD + n] - v;
                    float nll = 0.5f * (LOG2PI_C + d * d);
                    s += nll * aux2[m >> 3];
                }
            }
        }
        __shared__ float red[256];
        red[tid] = s;
        __syncthreads();
        for (int o = 128; o > 0; o >>= 1) {
            if (tid < o) red[tid] += red[tid + o];
            __syncthreads();
        }
        if (tid == 0) part[blockIdx.y * gridDim.x + blockIdx.x] = red[0];
    }
}

// ---------------- per-step kernel 2: drift layer2 + Euler + minmax --------
// 64 blocks x 256 threads; block handles 8 rows x all 256 cols; one warp/row
__global__ void __launch_bounds__(256) step2_kernel(
    int t, const float* __restrict__ w2, const float* __restrict__ b2,
    const float* __restrict__ noise)
{
    const int r = threadIdx.x >> 5;
    const int lane = threadIdx.x & 31;
    const int m = blockIdx.x * 8 + r;
    const int b = m >> 3;
    const float* Azw = g_zw + (size_t)t * BSZ * HH;
    const float* hp  = g_hpost + (size_t)t * BB * HH;

    __shared__ float Ws[16][256];
    __shared__ float As[8][16];
    float acc[8];
#pragma unroll
    for (int j = 0; j < 8; j++) acc[j] = 0.f;

    for (int k0 = 0; k0 < HH; k0 += 16) {
#pragma unroll
        for (int i = 0; i < 4; i++) {
            int f4 = threadIdx.x + 256 * i;
            int kr = f4 >> 6;
            int nc = (f4 & 63) << 2;
            *(float4*)&Ws[kr][nc] = *(const float4*)&w2[(size_t)(k0 + kr) * ZZ + nc];
        }
        if (threadIdx.x < 128) {
            int rr = threadIdx.x >> 4, kc = threadIdx.x & 15;
            int mm = blockIdx.x * 8 + rr;
            float v = Azw[(size_t)mm * HH + k0 + kc] +
                      hp[(size_t)(mm >> 3) * HH + k0 + kc];
            As[rr][kc] = fmaxf(v, 0.f);
        }
        __syncthreads();
#pragma unroll
        for (int kk = 0; kk < 16; kk++) {
            float a = As[r][kk];
            float4 wa = *(float4*)&Ws[kk][lane * 4];
            float4 wb = *(float4*)&Ws[kk][128 + lane * 4];
            acc[0] += a * wa.x; acc[1] += a * wa.y; acc[2] += a * wa.z; acc[3] += a * wa.w;
            acc[4] += a * wb.x; acc[5] += a * wb.y; acc[6] += a * wb.z; acc[7] += a * wb.w;
        }
        __syncthreads();
    }

    const float* zrow = g_states + (size_t)t * BSZ * ZZ + (size_t)m * ZZ;
    const float* nrow = noise + (size_t)t * BSZ * ZZ + (size_t)m * ZZ;
    const float* drow = g_diff + ((size_t)t * BB + b) * ZZ;
    float* prow = g_post + (size_t)t * BSZ * ZZ + (size_t)m * ZZ;
    float* orow = g_states + (size_t)(t + 1) * BSZ * ZZ + (size_t)m * ZZ;

    float zp[8];
    float vmin = 3.4e38f, vmax = -3.4e38f;
#pragma unroll
    for (int j = 0; j < 8; j++) {
        int n = (j < 4) ? lane * 4 + j : 128 + lane * 4 + (j - 4);
        float pd = 0.1f * tanhf(acc[j] + b2[n]);
        prow[n] = pd;
        float v = zrow[n] + DT_C * pd + SQRT_DT_C * drow[n] * nrow[n];
        zp[j] = v;
        vmin = fminf(vmin, v);
        vmax = fmaxf(vmax, v);
    }
#pragma unroll
    for (int o = 16; o > 0; o >>= 1) {
        vmin = fminf(vmin, __shfl_xor_sync(0xffffffffu, vmin, o));
        vmax = fmaxf(vmax, __shfl_xor_sync(0xffffffffu, vmax, o));
    }
    float inv = 1.f / (vmax - vmin);
#pragma unroll
    for (int j = 0; j < 8; j++) {
        int n = (j < 4) ? lane * 4 + j : 128 + lane * 4 + (j - 4);
        orow[n] = (zp[j] - vmin) * inv;
    }
}

// ---------------- small kernels ----------------
__global__ void mt_kernel(const float* __restrict__ M)
{
    int r = blockIdx.x * blockDim.x + threadIdx.x;
    if (r < TT * BB) {
        const float* p = M + (size_t)r * DD;
        float s = 0.f;
        for (int d = 0; d < DD; d++) s += p[d];
        g_Mt[r] = s * (1.f / DD);
    }
}

__global__ void z0_kernel(const float* __restrict__ cov,
                          const float* __restrict__ w1, const float* __restrict__ b1,
                          const float* __restrict__ w2, const float* __restrict__ b2)
{
    int b = blockIdx.x;
    __shared__ float cv[16];
    __shared__ float hid[64];
    if (threadIdx.x < 16) cv[threadIdx.x] = cov[b * 16 + threadIdx.x];
    __syncthreads();
    if (threadIdx.x < 64) {
        float s = b1[threadIdx.x];
        for (int i = 0; i < 16; i++) s += cv[i] * w1[i * 64 + threadIdx.x];
        hid[threadIdx.x] = fmaxf(s, 0.f);
    }
    __syncthreads();
    int n = threadIdx.x;
    float s = b2[n];
    for (int j = 0; j < 64; j++) s += hid[j] * w2[j * 256 + n];
    float z = tanhf(s);
    for (int ss = 0; ss < SS; ss++)
        g_states[(size_t)(b * SS + ss) * ZZ + n] = z;
}

__global__ void out_copy_kernel(float* __restrict__ out)
{
    int i = blockIdx.x * 256 + threadIdx.x;
    out[i] = g_states[(size_t)TT * BSZ * ZZ + i];
}

__global__ void scal_kernel(float* __restrict__ out)
{
    __shared__ float red[256];
    int tid = threadIdx.x;
    float s = 0.f;
    for (int i = tid; i < KLD_PARTS; i += 256) s += g_kld_part[i];
    red[tid] = s;
    __syncthreads();
    for (int o = 128; o > 0; o >>= 1) { if (tid < o) red[tid] += red[tid + o]; __syncthreads(); }
    float kldsum = red[0];
    __syncthreads();
    s = 0.f;
    for (int i = tid; i < RECON_PARTS; i += 256) s += g_recon_part[i];
    red[tid] = s;
    __syncthreads();
    for (int o = 128; o > 0; o >>= 1) { if (tid < o) red[tid] += red[tid + o]; __syncthreads(); }
    if (tid == 0) {
        float reconsum = red[0];
        float lk = (0.5f * DT_C / (float)(BB * SS)) * kldsum;
        float lr = reconsum * (1.f / (float)(BB * SS));
        out[131072] = lr + lk;   // loss_total
        out[131073] = lr;        // loss_recon
        out[131074] = lk;        // loss_kld
    }
}

// ---------------- launch ----------------
extern "C" void kernel_launch(void* const* d_in, const int* in_sizes, int n_in,
                              void* d_out, int out_size)
{
    (void)in_sizes; (void)n_in; (void)out_size;
    const float* X        = (const float*)d_in[0];
    const float* M        = (const float*)d_in[1];
    const float* cov      = (const float*)d_in[2];
    const float* path_h   = (const float*)d_in[3];
    const float* path_hpos= (const float*)d_in[4];
    const float* noise    = (const float*)d_in[5];
    const float* drift_w1 = (const float*)d_in[6];
    const float* drift_b1 = (const float*)d_in[7];
    const float* drift_w2 = (const float*)d_in[8];
    const float* drift_b2 = (const float*)d_in[9];
    const float* diff_w1  = (const float*)d_in[10];
    const float* diff_b1  = (const float*)d_in[11];
    const float* diff_w2  = (const float*)d_in[12];
    const float* diff_b2  = (const float*)d_in[13];
    const float* p_w1     = (const float*)d_in[14];
    const float* p_b1     = (const float*)d_in[15];
    const float* p_w2     = (const float*)d_in[16];
    const float* p_b2     = (const float*)d_in[17];
    const float* cov_w1   = (const float*)d_in[18];
    const float* cov_b1   = (const float*)d_in[19];
    const float* cov_w2   = (const float*)d_in[20];
    const float* cov_b2   = (const float*)d_in[21];
    float* out = (float*)d_out;

    float *hprior, *hpost, *ppart, *dtmp, *diffp, *states, *zw, *post, *A3, *kldp, *reconp, *Mtp;
    cudaGetSymbolAddress((void**)&hprior, g_hprior);
    cudaGetSymbolAddress((void**)&hpost,  g_hpost);
    cudaGetSymbolAddress((void**)&ppart,  g_ppart);
    cudaGetSymbolAddress((void**)&dtmp,   g_dtmp);
    cudaGetSymbolAddress((void**)&diffp,  g_diff);
    cudaGetSymbolAddress((void**)&states, g_states);
    cudaGetSymbolAddress((void**)&zw,     g_zw);
    cudaGetSymbolAddress((void**)&post,   g_post);
    cudaGetSymbolAddress((void**)&A3,     g_A3);
    cudaGetSymbolAddress((void**)&kldp,   g_kld_part);
    cudaGetSymbolAddress((void**)&reconp, g_recon_part);
    cudaGetSymbolAddress((void**)&Mtp,    g_Mt);

    // ---- precompute (parallel over T) ----
    // hprior = path_h @ drift_w1[:R] + drift_b1
    gemm_k<PRO_PLAIN, EPI_STORE><<<dim3(16, 200), 256>>>(
        path_h, RR, drift_w1, HH, hprior, HH, RR, drift_b1,
        nullptr, nullptr, nullptr, nullptr);
    gemm_k<PRO_PLAIN, EPI_STORE><<<dim3(16, 200), 256>>>(
        path_hpos, RR, drift_w1, HH, hpost, HH, RR, drift_b1,
        nullptr, nullptr, nullptr, nullptr);
    gemm_k<PRO_PLAIN, EPI_STORE><<<dim3(16, 200), 256>>>(
        path_h, RR, p_w1, HH, ppart, HH, RR, p_b1,
        nullptr, nullptr, nullptr, nullptr);
    gemm_k<PRO_PLAIN, EPI_RELU><<<dim3(16, 200), 256>>>(
        path_h, RR, diff_w1, HH, dtmp, HH, RR, diff_b1,
        nullptr, nullptr, nullptr, nullptr);
    gemm_k<PRO_PLAIN, EPI_EXP><<<dim3(4, 200), 256>>>(
        dtmp, HH, diff_w2, ZZ, diffp, ZZ, HH, diff_b2,
        nullptr, nullptr, nullptr, nullptr);
    mt_kernel<<<(TT * BB + 255) / 256, 256>>>(M);
    z0_kernel<<<BB, 256>>>(cov, cov_w1, cov_b1, cov_w2, cov_b2);

    // ---- sequential scan (critical path: posterior branch only) ----
    for (int t = 0; t < TT; t++) {
        // S1: zw[t] = z_t @ drift_w1[R:]
        gemm_k<PRO_PLAIN, EPI_STORE><<<dim3(16, 8), 256>>>(
            states + (size_t)t * BSZ * ZZ, ZZ,
            drift_w1 + (size_t)RR * HH, HH,
            zw + (size_t)t * BSZ * HH, HH, ZZ, nullptr,
            nullptr, nullptr, nullptr, nullptr);
        // S2: posterior drift + Euler + minmax normalize
        step2_kernel<<<64, 256>>>(t, drift_w2, drift_b2, noise);
    }

    // ---- batch epilogue (parallel over all T) ----
    // P2: prior drift + fused KLD reduction (reuses stored zw)
    gemm_k<PRO_ADDRELU, EPI_KLD><<<dim3(4, 1600), 256>>>(
        zw, HH, drift_w2, ZZ, nullptr, 0, HH, drift_b2,
        hprior, post, diffp, kldp);
    // P3: decoder hidden = relu(ppart + z_new @ p_w1[R:])
    gemm_k<PRO_PLAIN, EPI_BCASTRELU><<<dim3(16, 1600), 256>>>(
        states + (size_t)BSZ * ZZ, ZZ, p_w1 + (size_t)RR * HH, HH,
        A3, HH, ZZ, nullptr, ppart, nullptr, nullptr, nullptr);
    // P4: decoder output + fused recon reduction
    gemm_k<PRO_PLAIN, EPI_RECON><<<dim3(2, 1600), 256>>>(
        A3, HH, p_w2, DD, nullptr, 0, HH, p_b2,
        X, Mtp, nullptr, reconp);

    // ---- output: z_final then (total, recon, kld) ----
    out_copy_kernel<<<512, 256>>>(out);
    scal_kernel<<<1, 256>>>(out);
}

// round 4
// speedup vs baseline: 1.8558x; 1.8558x over previous
#include <cuda_runtime.h>
#include <math.h>

#define TT 200
#define BB 64
#define SS 8
#define DD 128
#define RR 512
#define ZZ 256
#define HH 1024
#define BSZ (BB*SS)            /* 512 rows per step */
#define DT_C 0.05f
#define SQRT_DT_C 0.223606797749979f
#define LOG2PI_C 1.8378770664093453f

#define KLD_PARTS  (1600*4)
#define RECON_PARTS (1600*2)

#define SCAN_BLOCKS 128
#define SCAN_THREADS 256

// ---------------- device scratch (static, allocation-free) ----------------
__device__ float g_hprior[TT*BB*HH];        // h@drift_w1[:R] + b1
__device__ float g_hpost [TT*BB*HH];        // hpos@drift_w1[:R] + b1
__device__ float g_ppart [TT*BB*HH];        // h@p_w1[:R] + p_b1
__device__ float g_dtmp  [TT*BB*HH];        // relu(h@diff_w1+b1)
__device__ float g_diff  [TT*BB*ZZ];        // exp(diff MLP)
__device__ float g_Mt    [TT*BB];
__device__ float g_states[(TT+1)*BSZ*ZZ];   // z trajectory (normalized)
__device__ float g_zw    [TT*BSZ*HH];       // z_t @ drift_w1[R:]
__device__ float g_post  [TT*BSZ*ZZ];       // posterior drift
__device__ float g_A3    [TT*BSZ*HH];       // decoder hidden
__device__ float g_part  [4*BSZ*ZZ];        // split-K partials for scan
__device__ float g_kld_part[KLD_PARTS];
__device__ float g_recon_part[RECON_PARTS];
__device__ unsigned g_barcnt;

// ---------------- generic 64x64 fp32 GEMM with fused pro/epilogues --------
#define PRO_PLAIN 0
#define PRO_ADDRELU 1      // A := relu(A + aux[(m>>3)*H + k])
#define EPI_STORE 0        // C = acc (+bias)
#define EPI_RELU  1
#define EPI_EXP   2
#define EPI_BCASTRELU 3    // C = relu(acc + aux[(m>>3)*H + n])
#define EPI_KLD   4        // reduce ((0.1 tanh(acc+b)-post)/diff)^2
#define EPI_RECON 5        // reduce 0.5(log2pi+(X-(acc+b))^2)*Mt

template<int PRO, int EPI>
__global__ void __launch_bounds__(256) gemm_k(
    const float* __restrict__ A, int lda,
    const float* __restrict__ Bm, int ldb,
    float* __restrict__ C, int ldc, int K,
    const float* __restrict__ bias,
    const float* __restrict__ aux,
    const float* __restrict__ aux2,
    const float* __restrict__ aux3,
    float* __restrict__ part)
{
    __shared__ float As[16][64];
    __shared__ float Bs[16][64];
    const int tid = threadIdx.x;
    const int tx = tid & 15, ty = tid >> 4;
    const int m0 = blockIdx.y * 64, n0 = blockIdx.x * 64;
    const int arow = tid >> 2;            // 0..63
    const int ak4  = (tid & 3) << 2;      // 0,4,8,12
    const int brow = tid >> 4;            // 0..15
    const int bn4  = (tid & 15) << 2;

    float acc[4][4];
#pragma unroll
    for (int i = 0; i < 4; i++)
#pragma unroll
        for (int j = 0; j < 4; j++) acc[i][j] = 0.f;

    for (int k0 = 0; k0 < K; k0 += 16) {
        float4 av = *(const float4*)&A[(size_t)(m0 + arow) * lda + k0 + ak4];
        if (PRO == PRO_ADDRELU) {
            const float4 hv = *(const float4*)&aux[(size_t)((m0 + arow) >> 3) * HH + k0 + ak4];
            av.x = fmaxf(av.x + hv.x, 0.f); av.y = fmaxf(av.y + hv.y, 0.f);
            av.z = fmaxf(av.z + hv.z, 0.f); av.w = fmaxf(av.w + hv.w, 0.f);
        }
        As[ak4 + 0][arow] = av.x; As[ak4 + 1][arow] = av.y;
        As[ak4 + 2][arow] = av.z; As[ak4 + 3][arow] = av.w;
        *(float4*)&Bs[brow][bn4] =
            *(const float4*)&Bm[(size_t)(k0 + brow) * ldb + n0 + bn4];
        __syncthreads();
#pragma unroll
        for (int kk = 0; kk < 16; kk++) {
            float4 a = *(float4*)&As[kk][ty * 4];
            float4 b = *(float4*)&Bs[kk][tx * 4];
            acc[0][0] += a.x * b.x; acc[0][1] += a.x * b.y; acc[0][2] += a.x * b.z; acc[0][3] += a.x * b.w;
            acc[1][0] += a.y * b.x; acc[1][1] += a.y * b.y; acc[1][2] += a.y * b.z; acc[1][3] += a.y * b.w;
            acc[2][0] += a.z * b.x; acc[2][1] += a.z * b.y; acc[2][2] += a.z * b.z; acc[2][3] += a.z * b.w;
            acc[3][0] += a.w * b.x; acc[3][1] += a.w * b.y; acc[3][2] += a.w * b.z; acc[3][3] += a.w * b.w;
        }
        __syncthreads();
    }

    if (EPI <= 3) {
        const bool hasb = (bias != nullptr);
#pragma unroll
        for (int i = 0; i < 4; i++) {
            const int m = m0 + ty * 4 + i;
#pragma unroll
            for (int j = 0; j < 4; j++) {
                const int n = n0 + tx * 4 + j;
                float v = acc[i][j];
                if (hasb) v += bias[n];
                if (EPI == EPI_RELU) v = fmaxf(v, 0.f);
                if (EPI == EPI_EXP)  v = expf(v);
                if (EPI == EPI_BCASTRELU)
                    v = fmaxf(v + aux[(size_t)(m >> 3) * HH + n], 0.f);
                C[(size_t)m * ldc + n] = v;
            }
        }
    } else {
        float s = 0.f;
#pragma unroll
        for (int i = 0; i < 4; i++) {
            const int m = m0 + ty * 4 + i;
#pragma unroll
            for (int j = 0; j < 4; j++) {
                const int n = n0 + tx * 4 + j;
                float v = acc[i][j] + bias[n];
                if (EPI == EPI_KLD) {
                    float pr = 0.1f * tanhf(v);
                    float e = (pr - aux2[(size_t)m * ZZ + n]) /
                              aux3[(size_t)(m >> 3) * ZZ + n];
                    s += e * e;
                } else { // EPI_RECON
                    float d = aux[(size_t)(m >> 3) * DD + n] - v;
                    float nll = 0.5f * (LOG2PI_C + d * d);
                    s += nll * aux2[m >> 3];
                }
            }
        }
        __shared__ float red[256];
        red[tid] = s;
        __syncthreads();
        for (int o = 128; o > 0; o >>= 1) {
            if (tid < o) red[tid] += red[tid + o];
            __syncthreads();
        }
        if (tid == 0) part[blockIdx.y * gridDim.x + blockIdx.x] = red[0];
    }
}

// ---------------- persistent scan kernel ----------------
// 128 blocks x 256 threads. Per-block persistent smem:
//   W1s: drift_w1[R:] slice 256 x 32 cols (stride 36)   = 36864 B
//   W2s: drift_w2 slice   256k x 64 cols (stride 68)    = 69632 B
//   As : z stage      [16][132]                         =  8448 B
//   As2: hidden stage [16][68]                          =  4352 B
#define SMEM_SCAN ((256*36 + 256*68 + 16*132 + 16*68) * 4)

__device__ __forceinline__ void gridbar(unsigned& tgt)
{
    __syncthreads();
    if (threadIdx.x == 0) {
        __threadfence();
        atomicAdd(&g_barcnt, 1u);
        tgt += SCAN_BLOCKS;
        while (*(volatile unsigned*)&g_barcnt < tgt) { }
        __threadfence();
    }
    __syncthreads();
}

__global__ void __launch_bounds__(SCAN_THREADS, 1) scan_kernel(
    const float* __restrict__ w1z,      // drift_w1 + RR*HH
    const float* __restrict__ w2,       // drift_w2
    const float* __restrict__ b2,       // drift_b2
    const float* __restrict__ noise)
{
    extern __shared__ float sm[];
    float* W1s = sm;                       // [256][36]
    float* W2s = sm + 256*36;              // [256][68]
    float* As  = sm + 256*36 + 256*68;     // [16][132]
    float* As2 = As + 16*132;              // [16][68]

    const int tid = threadIdx.x;
    const int bid = blockIdx.x;

    // phase A geometry: 4 m-tiles (128 rows) x 32 n-tiles (32 cols of 1024)
    const int bmA = bid >> 5;
    const int bnA = bid & 31;
    const int tyA = tid >> 3;      // 0..31 -> rows*4
    const int txA = tid & 7;       // 0..7  -> cols*4

    // phase B1 geometry: 8 m-tiles(64r) x 4 n-tiles(64c) x 4 k-chunks(256)
    const int kcB = bid & 3;
    const int moB = (bid >> 2) >> 2;   // 0..7
    const int noB = (bid >> 2) & 3;    // 0..3
    const int tyB = tid >> 4;          // 0..15 -> rows*4
    const int txB = tid & 15;          // 0..15 -> cols*4

    // load persistent weight slices
    for (int i = tid; i < 256*32; i += SCAN_THREADS) {
        int k = i >> 5, c = i & 31;
        W1s[k*36 + c] = w1z[(size_t)k*HH + bnA*32 + c];
    }
    for (int i = tid; i < 256*64; i += SCAN_THREADS) {
        int k = i >> 6, c = i & 63;
        W2s[k*68 + c] = w2[(size_t)(kcB*256 + k)*ZZ + noB*64 + c];
    }
    __syncthreads();

    unsigned tgt = 0;
    const int wid = tid >> 5, lane = tid & 31;

    for (int t = 0; t < TT; t++) {
        // ============ phase A: zw[t] = z_t @ w1z ============
        const float* z = g_states + (size_t)t*BSZ*ZZ;
        float* zwt = g_zw + (size_t)t*BSZ*HH;
        {
            float acc[4][4];
#pragma unroll
            for (int i = 0; i < 4; i++)
#pragma unroll
                for (int j = 0; j < 4; j++) acc[i][j] = 0.f;

            for (int k0 = 0; k0 < ZZ; k0 += 16) {
#pragma unroll
                for (int r = 0; r < 2; r++) {
                    int v = tid + SCAN_THREADS*r;
                    int row = v >> 2, kq = (v & 3) << 2;
                    float4 f = *(const float4*)&z[(size_t)(bmA*128 + row)*ZZ + k0 + kq];
                    As[(kq+0)*132 + row] = f.x;
                    As[(kq+1)*132 + row] = f.y;
                    As[(kq+2)*132 + row] = f.z;
                    As[(kq+3)*132 + row] = f.w;
                }
                __syncthreads();
#pragma unroll
                for (int kk = 0; kk < 16; kk++) {
                    float4 a = *(float4*)&As[kk*132 + tyA*4];
                    float4 b = *(float4*)&W1s[(k0+kk)*36 + txA*4];
                    acc[0][0] += a.x*b.x; acc[0][1] += a.x*b.y; acc[0][2] += a.x*b.z; acc[0][3] += a.x*b.w;
                    acc[1][0] += a.y*b.x; acc[1][1] += a.y*b.y; acc[1][2] += a.y*b.z; acc[1][3] += a.y*b.w;
                    acc[2][0] += a.z*b.x; acc[2][1] += a.z*b.y; acc[2][2] += a.z*b.z; acc[2][3] += a.z*b.w;
                    acc[3][0] += a.w*b.x; acc[3][1] += a.w*b.y; acc[3][2] += a.w*b.z; acc[3][3] += a.w*b.w;
                }
                __syncthreads();
            }
#pragma unroll
            for (int i = 0; i < 4; i++) {
                float4 o = make_float4(acc[i][0], acc[i][1], acc[i][2], acc[i][3]);
                *(float4*)&zwt[(size_t)(bmA*128 + tyA*4 + i)*HH + bnA*32 + txA*4] = o;
            }
        }
        gridbar(tgt);

        // ============ phase B1: partial relu(zw+hpost)@W2 (split-K) ============
        {
            const float* hp = g_hpost + (size_t)t*BB*HH;
            float acc[4][4];
#pragma unroll
            for (int i = 0; i < 4; i++)
#pragma unroll
                for (int j = 0; j < 4; j++) acc[i][j] = 0.f;

            for (int k0 = 0; k0 < 256; k0 += 16) {
                {
                    int row = tid >> 2, kq = (tid & 3) << 2;
                    int gk = kcB*256 + k0 + kq;
                    float4 f = *(const float4*)&zwt[(size_t)(moB*64 + row)*HH + gk];
                    float4 h = *(const float4*)&hp[(size_t)((moB*64 + row) >> 3)*HH + gk];
                    As2[(kq+0)*68 + row] = fmaxf(f.x + h.x, 0.f);
                    As2[(kq+1)*68 + row] = fmaxf(f.y + h.y, 0.f);
                    As2[(kq+2)*68 + row] = fmaxf(f.z + h.z, 0.f);
                    As2[(kq+3)*68 + row] = fmaxf(f.w + h.w, 0.f);
                }
                __syncthreads();
#pragma unroll
                for (int kk = 0; kk < 16; kk++) {
                    float4 a = *(float4*)&As2[kk*68 + tyB*4];
                    float4 b = *(float4*)&W2s[(k0+kk)*68 + txB*4];
                    acc[0][0] += a.x*b.x; acc[0][1] += a.x*b.y; acc[0][2] += a.x*b.z; acc[0][3] += a.x*b.w;
                    acc[1][0] += a.y*b.x; acc[1][1] += a.y*b.y; acc[1][2] += a.y*b.z; acc[1][3] += a.y*b.w;
                    acc[2][0] += a.z*b.x; acc[2][1] += a.z*b.y; acc[2][2] += a.z*b.z; acc[2][3] += a.z*b.w;
                    acc[3][0] += a.w*b.x; acc[3][1] += a.w*b.y; acc[3][2] += a.w*b.z; acc[3][3] += a.w*b.w;
                }
                __syncthreads();
            }
            float* gp = g_part + (size_t)kcB*BSZ*ZZ;
#pragma unroll
            for (int i = 0; i < 4; i++) {
                float4 o = make_float4(acc[i][0], acc[i][1], acc[i][2], acc[i][3]);
                *(float4*)&gp[(size_t)(moB*64 + tyB*4 + i)*ZZ + noB*64 + txB*4] = o;
            }
        }
        gridbar(tgt);

        // ============ phase B2: combine + tanh + Euler + row minmax ============
        if (wid < 4) {
            const int row = bid*4 + wid;
            const float* zr = g_states + (size_t)t*BSZ*ZZ + (size_t)row*ZZ;
            const float* nr = noise + (size_t)t*BSZ*ZZ + (size_t)row*ZZ;
            const float* dr = g_diff + ((size_t)t*BB + (row >> 3))*ZZ;
            float* pr = g_post + (size_t)t*BSZ*ZZ + (size_t)row*ZZ;
            float* outz = g_states + (size_t)(t+1)*BSZ*ZZ + (size_t)row*ZZ;

            float v8[8];
            float vmin = 3.4e38f, vmax = -3.4e38f;
#pragma unroll
            for (int j = 0; j < 2; j++) {
                const int cb = lane*4 + 128*j;
                float4 s  = *(const float4*)&g_part[0*BSZ*ZZ + (size_t)row*ZZ + cb];
                float4 s1 = *(const float4*)&g_part[1*BSZ*ZZ + (size_t)row*ZZ + cb];
                float4 s2 = *(const float4*)&g_part[2*BSZ*ZZ + (size_t)row*ZZ + cb];
                float4 s3 = *(const float4*)&g_part[3*BSZ*ZZ + (size_t)row*ZZ + cb];
                float4 bb = *(const float4*)&b2[cb];
                float4 zv = *(const float4*)&zr[cb];
                float4 nv = *(const float4*)&nr[cb];
                float4 dv = *(const float4*)&dr[cb];
                float pd0 = 0.1f * tanhf(s.x + s1.x + s2.x + s3.x + bb.x);
                float pd1 = 0.1f * tanhf(s.y + s1.y + s2.y + s3.y + bb.y);
                float pd2 = 0.1f * tanhf(s.z + s1.z + s2.z + s3.z + bb.z);
                float pd3 = 0.1f * tanhf(s.w + s1.w + s2.w + s3.w + bb.w);
                *(float4*)&pr[cb] = make_float4(pd0, pd1, pd2, pd3);
                float n0v = zv.x + DT_C*pd0 + SQRT_DT_C*dv.x*nv.x;
                float n1v = zv.y + DT_C*pd1 + SQRT_DT_C*dv.y*nv.y;
                float n2v = zv.z + DT_C*pd2 + SQRT_DT_C*dv.z*nv.z;
                float n3v = zv.w + DT_C*pd3 + SQRT_DT_C*dv.w*nv.w;
                v8[j*4+0] = n0v; v8[j*4+1] = n1v; v8[j*4+2] = n2v; v8[j*4+3] = n3v;
                vmin = fminf(vmin, fminf(fminf(n0v, n1v), fminf(n2v, n3v)));
                vmax = fmaxf(vmax, fmaxf(fmaxf(n0v, n1v), fmaxf(n2v, n3v)));
            }
#pragma unroll
            for (int o = 16; o > 0; o >>= 1) {
                vmin = fminf(vmin, __shfl_xor_sync(0xffffffffu, vmin, o));
                vmax = fmaxf(vmax, __shfl_xor_sync(0xffffffffu, vmax, o));
            }
            const float inv = 1.f / (vmax - vmin);
#pragma unroll
            for (int j = 0; j < 2; j++) {
                const int cb = lane*4 + 128*j;
                *(float4*)&outz[cb] = make_float4((v8[j*4+0]-vmin)*inv, (v8[j*4+1]-vmin)*inv,
                                                  (v8[j*4+2]-vmin)*inv, (v8[j*4+3]-vmin)*inv);
            }
        }
        gridbar(tgt);
    }
}

// ---------------- small kernels ----------------
__global__ void reset_kernel() { g_barcnt = 0u; }

__global__ void mt_kernel(const float* __restrict__ M)
{
    int r = blockIdx.x * blockDim.x + threadIdx.x;
    if (r < TT * BB) {
        const float* p = M + (size_t)r * DD;
        float s = 0.f;
        for (int d = 0; d < DD; d++) s += p[d];
        g_Mt[r] = s * (1.f / DD);
    }
}

__global__ void z0_kernel(const float* __restrict__ cov,
                          const float* __restrict__ w1, const float* __restrict__ b1,
                          const float* __restrict__ w2, const float* __restrict__ b2)
{
    int b = blockIdx.x;
    __shared__ float cv[16];
    __shared__ float hid[64];
    if (threadIdx.x < 16) cv[threadIdx.x] = cov[b * 16 + threadIdx.x];
    __syncthreads();
    if (threadIdx.x < 64) {
        float s = b1[threadIdx.x];
        for (int i = 0; i < 16; i++) s += cv[i] * w1[i * 64 + threadIdx.x];
        hid[threadIdx.x] = fmaxf(s, 0.f);
    }
    __syncthreads();
    int n = threadIdx.x;
    float s = b2[n];
    for (int j = 0; j < 64; j++) s += hid[j] * w2[j * 256 + n];
    float z = tanhf(s);
    for (int ss = 0; ss < SS; ss++)
        g_states[(size_t)(b * SS + ss) * ZZ + n] = z;
}

__global__ void out_copy_kernel(float* __restrict__ out)
{
    int i = blockIdx.x * 256 + threadIdx.x;
    out[i] = g_states[(size_t)TT * BSZ * ZZ + i];
}

__global__ void scal_kernel(float* __restrict__ out)
{
    __shared__ float red[256];
    int tid = threadIdx.x;
    float s = 0.f;
    for (int i = tid; i < KLD_PARTS; i += 256) s += g_kld_part[i];
    red[tid] = s;
    __syncthreads();
    for (int o = 128; o > 0; o >>= 1) { if (tid < o) red[tid] += red[tid + o]; __syncthreads(); }
    float kldsum = red[0];
    __syncthreads();
    s = 0.f;
    for (int i = tid; i < RECON_PARTS; i += 256) s += g_recon_part[i];
    red[tid] = s;
    __syncthreads();
    for (int o = 128; o > 0; o >>= 1) { if (tid < o) red[tid] += red[tid + o]; __syncthreads(); }
    if (tid == 0) {
        float reconsum = red[0];
        float lk = (0.5f * DT_C / (float)(BB * SS)) * kldsum;
        float lr = reconsum * (1.f / (float)(BB * SS));
        out[131072] = lr + lk;   // loss_total
        out[131073] = lr;        // loss_recon
        out[131074] = lk;        // loss_kld
    }
}

// ---------------- launch ----------------
extern "C" void kernel_launch(void* const* d_in, const int* in_sizes, int n_in,
                              void* d_out, int out_size)
{
    (void)in_sizes; (void)n_in; (void)out_size;
    const float* X        = (const float*)d_in[0];
    const float* M        = (const float*)d_in[1];
    const float* cov      = (const float*)d_in[2];
    const float* path_h   = (const float*)d_in[3];
    const float* path_hpos= (const float*)d_in[4];
    const float* noise    = (const float*)d_in[5];
    const float* drift_w1 = (const float*)d_in[6];
    const float* drift_b1 = (const float*)d_in[7];
    const float* drift_w2 = (const float*)d_in[8];
    const float* drift_b2 = (const float*)d_in[9];
    const float* diff_w1  = (const float*)d_in[10];
    const float* diff_b1  = (const float*)d_in[11];
    const float* diff_w2  = (const float*)d_in[12];
    const float* diff_b2  = (const float*)d_in[13];
    const float* p_w1     = (const float*)d_in[14];
    const float* p_b1     = (const float*)d_in[15];
    const float* p_w2     = (const float*)d_in[16];
    const float* p_b2     = (const float*)d_in[17];
    const float* cov_w1   = (const float*)d_in[18];
    const float* cov_b1   = (const float*)d_in[19];
    const float* cov_w2   = (const float*)d_in[20];
    const float* cov_b2   = (const float*)d_in[21];
    float* out = (float*)d_out;

    float *hprior, *hpost, *ppart, *dtmp, *diffp, *states, *zw, *post, *A3, *kldp, *reconp, *Mtp;
    cudaGetSymbolAddress((void**)&hprior, g_hprior);
    cudaGetSymbolAddress((void**)&hpost,  g_hpost);
    cudaGetSymbolAddress((void**)&ppart,  g_ppart);
    cudaGetSymbolAddress((void**)&dtmp,   g_dtmp);
    cudaGetSymbolAddress((void**)&diffp,  g_diff);
    cudaGetSymbolAddress((void**)&states, g_states);
    cudaGetSymbolAddress((void**)&zw,     g_zw);
    cudaGetSymbolAddress((void**)&post,   g_post);
    cudaGetSymbolAddress((void**)&A3,     g_A3);
    cudaGetSymbolAddress((void**)&kldp,   g_kld_part);
    cudaGetSymbolAddress((void**)&reconp, g_recon_part);
    cudaGetSymbolAddress((void**)&Mtp,    g_Mt);

    static int smem_set = 0;
    if (!smem_set) {
        cudaFuncSetAttribute(scan_kernel,
                             cudaFuncAttributeMaxDynamicSharedMemorySize, SMEM_SCAN);
        smem_set = 1;
    }

    // ---- precompute (parallel over T) ----
    reset_kernel<<<1, 1>>>();
    gemm_k<PRO_PLAIN, EPI_STORE><<<dim3(16, 200), 256>>>(
        path_h, RR, drift_w1, HH, hprior, HH, RR, drift_b1,
        nullptr, nullptr, nullptr, nullptr);
    gemm_k<PRO_PLAIN, EPI_STORE><<<dim3(16, 200), 256>>>(
        path_hpos, RR, drift_w1, HH, hpost, HH, RR, drift_b1,
        nullptr, nullptr, nullptr, nullptr);
    gemm_k<PRO_PLAIN, EPI_STORE><<<dim3(16, 200), 256>>>(
        path_h, RR, p_w1, HH, ppart, HH, RR, p_b1,
        nullptr, nullptr, nullptr, nullptr);
    gemm_k<PRO_PLAIN, EPI_RELU><<<dim3(16, 200), 256>>>(
        path_h, RR, diff_w1, HH, dtmp, HH, RR, diff_b1,
        nullptr, nullptr, nullptr, nullptr);
    gemm_k<PRO_PLAIN, EPI_EXP><<<dim3(4, 200), 256>>>(
        dtmp, HH, diff_w2, ZZ, diffp, ZZ, HH, diff_b2,
        nullptr, nullptr, nullptr, nullptr);
    mt_kernel<<<(TT * BB + 255) / 256, 256>>>(M);
    z0_kernel<<<BB, 256>>>(cov, cov_w1, cov_b1, cov_w2, cov_b2);

    // ---- sequential scan: ONE persistent kernel for all 200 steps ----
    scan_kernel<<<SCAN_BLOCKS, SCAN_THREADS, SMEM_SCAN>>>(
        drift_w1 + (size_t)RR * HH, drift_w2, drift_b2, noise);

    // ---- batch epilogue (parallel over all T) ----
    gemm_k<PRO_ADDRELU, EPI_KLD><<<dim3(4, 1600), 256>>>(
        zw, HH, drift_w2, ZZ, nullptr, 0, HH, drift_b2,
        hprior, post, diffp, kldp);
    gemm_k<PRO_PLAIN, EPI_BCASTRELU><<<dim3(16, 1600), 256>>>(
        states + (size_t)BSZ * ZZ, ZZ, p_w1 + (size_t)RR * HH, HH,
        A3, HH, ZZ, nullptr, ppart, nullptr, nullptr, nullptr);
    gemm_k<PRO_PLAIN, EPI_RECON><<<dim3(2, 1600), 256>>>(
        A3, HH, p_w2, DD, nullptr, 0, HH, p_b2,
        X, Mtp, nullptr, reconp);

    // ---- output: z_final then (total, recon, kld) ----
    out_copy_kernel<<<512, 256>>>(out);
    scal_kernel<<<1, 256>>>(out);
}

// round 5
// speedup vs baseline: 2.5059x; 1.3503x over previous
#include <cuda_runtime.h>
#include <math.h>
#include <stdint.h>

#define TT 200
#define BB 64
#define SS 8
#define DD 128
#define RR 512
#define ZZ 256
#define HH 1024
#define BSZ (BB*SS)            /* 512 rows per step */
#define DT_C 0.05f
#define SQRT_DT_C 0.223606797749979f
#define LOG2PI_C 1.8378770664093453f

#define KLD_PARTS  (1600*4)
#define RECON_PARTS (1600*2)

#define SCAN_BLOCKS 128
#define SCAN_THREADS 256

// ---------------- device scratch (static, allocation-free) ----------------
__device__ float g_hprior[TT*BB*HH];        // h@drift_w1[:R] + b1
__device__ float g_hpost [TT*BB*HH];        // hpos@drift_w1[:R] + b1
__device__ float g_ppart [TT*BB*HH];        // h@p_w1[:R] + p_b1
__device__ float g_dtmp  [TT*BB*HH];        // relu(h@diff_w1+b1)
__device__ float g_diff  [TT*BB*ZZ];        // exp(diff MLP)
__device__ float g_Mt    [TT*BB];
__device__ float g_states[(TT+1)*BSZ*ZZ];   // z trajectory (normalized)
__device__ float g_zw    [TT*BSZ*HH];       // z_t @ drift_w1[R:]
__device__ float g_post  [TT*BSZ*ZZ];       // posterior drift
__device__ float g_A3    [TT*BSZ*HH];       // decoder hidden
__device__ float g_part  [4*BSZ*ZZ];        // split-K partials for scan
__device__ float g_kld_part[KLD_PARTS];
__device__ float g_recon_part[RECON_PARTS];
__device__ unsigned g_barcnt;

// ---------------- tf32 helpers ----------------
__device__ __forceinline__ uint32_t f2tf(float f)
{
    uint32_t u;
    asm("cvt.rna.tf32.f32 %0, %1;" : "=r"(u) : "f"(f));
    return u;
}

__device__ __forceinline__ void mma8(float* c,
    uint32_t a0, uint32_t a1, uint32_t a2, uint32_t a3,
    uint32_t b0, uint32_t b1)
{
    asm("mma.sync.aligned.m16n8k8.row.col.f32.tf32.tf32.f32 "
        "{%0,%1,%2,%3},{%4,%5,%6,%7},{%8,%9},{%0,%1,%2,%3};"
        : "+f"(c[0]), "+f"(c[1]), "+f"(c[2]), "+f"(c[3])
        : "r"(a0), "r"(a1), "r"(a2), "r"(a3), "r"(b0), "r"(b1));
}

// ---------------- generic 64x64 tf32 GEMM with fused pro/epilogues ------
#define PRO_PLAIN 0
#define PRO_ADDRELU 1      // A := relu(A + aux[(m>>3)*H + k])
#define EPI_STORE 0        // C = acc (+bias)
#define EPI_RELU  1
#define EPI_EXP   2
#define EPI_BCASTRELU 3    // C = relu(acc + aux[(m>>3)*H + n])
#define EPI_KLD   4        // reduce ((0.1 tanh(acc+b)-post)/diff)^2
#define EPI_RECON 5        // reduce 0.5(log2pi+(X-(acc+b))^2)*Mt

template<int PRO, int EPI>
__global__ void __launch_bounds__(256) gemm_t(
    const float* __restrict__ A, int lda,
    const float* __restrict__ Bm, int ldb,
    float* __restrict__ C, int ldc, int K,
    const float* __restrict__ bias,
    const float* __restrict__ aux,
    const float* __restrict__ aux2,
    const float* __restrict__ aux3,
    float* __restrict__ part)
{
    __shared__ uint32_t As[64][20];   // stride 20 -> conflict-free frag loads
    __shared__ uint32_t Bs[16][72];   // stride 72 -> conflict-free frag loads
    const int tid = threadIdx.x;
    const int m0 = blockIdx.y * 64, n0 = blockIdx.x * 64;
    const int wid = tid >> 5, lane = tid & 31;
    const int wm = (wid & 3) * 16;     // warp row offset in tile
    const int wn = (wid >> 2) * 32;    // warp col offset in tile
    const int qr = lane >> 2;          // 0..7
    const int qc = lane & 3;           // 0..3
    const int arow = tid >> 2;         // 0..63
    const int ak4  = (tid & 3) << 2;   // 0,4,8,12
    const int brow = tid >> 4;         // 0..15
    const int bn4  = (tid & 15) << 2;

    float acc[4][4];
#pragma unroll
    for (int j = 0; j < 4; j++)
#pragma unroll
        for (int c = 0; c < 4; c++) acc[j][c] = 0.f;

    for (int k0 = 0; k0 < K; k0 += 16) {
        float4 av = *(const float4*)&A[(size_t)(m0 + arow) * lda + k0 + ak4];
        if (PRO == PRO_ADDRELU) {
            const float4 hv = *(const float4*)&aux[(size_t)((m0 + arow) >> 3) * HH + k0 + ak4];
            av.x = fmaxf(av.x + hv.x, 0.f); av.y = fmaxf(av.y + hv.y, 0.f);
            av.z = fmaxf(av.z + hv.z, 0.f); av.w = fmaxf(av.w + hv.w, 0.f);
        }
        {
            uint4 t;
            t.x = f2tf(av.x); t.y = f2tf(av.y); t.z = f2tf(av.z); t.w = f2tf(av.w);
            *(uint4*)&As[arow][ak4] = t;
        }
        {
            float4 bv = *(const float4*)&Bm[(size_t)(k0 + brow) * ldb + n0 + bn4];
            uint4 t;
            t.x = f2tf(bv.x); t.y = f2tf(bv.y); t.z = f2tf(bv.z); t.w = f2tf(bv.w);
            *(uint4*)&Bs[brow][bn4] = t;
        }
        __syncthreads();
#pragma unroll
        for (int kk = 0; kk < 16; kk += 8) {
            uint32_t a0 = As[wm + qr    ][kk + qc];
            uint32_t a1 = As[wm + qr + 8][kk + qc];
            uint32_t a2 = As[wm + qr    ][kk + qc + 4];
            uint32_t a3 = As[wm + qr + 8][kk + qc + 4];
#pragma unroll
            for (int j = 0; j < 4; j++) {
                const int cn = wn + j * 8 + qr;
                mma8(acc[j], a0, a1, a2, a3, Bs[kk + qc][cn], Bs[kk + qc + 4][cn]);
            }
        }
        __syncthreads();
    }

    // epilogue: thread owns rows {mA, mA+8}, cols nBase+j*8 + {0,1}
    const int mA = m0 + wm + qr;
    const int nB0 = n0 + wn + qc * 2;

    if (EPI <= 3) {
        const bool hasb = (bias != nullptr);
#pragma unroll
        for (int j = 0; j < 4; j++) {
            const int n = nB0 + j * 8;
            float v[4] = {acc[j][0], acc[j][1], acc[j][2], acc[j][3]};
            const int mm[4] = {mA, mA, mA + 8, mA + 8};
            const int nn[4] = {n, n + 1, n, n + 1};
#pragma unroll
            for (int c = 0; c < 4; c++) {
                if (hasb) v[c] += bias[nn[c]];
                if (EPI == EPI_RELU) v[c] = fmaxf(v[c], 0.f);
                if (EPI == EPI_EXP)  v[c] = expf(v[c]);
                if (EPI == EPI_BCASTRELU)
                    v[c] = fmaxf(v[c] + aux[(size_t)(mm[c] >> 3) * HH + nn[c]], 0.f);
            }
            *(float2*)&C[(size_t)mA * ldc + n]       = make_float2(v[0], v[1]);
            *(float2*)&C[(size_t)(mA + 8) * ldc + n] = make_float2(v[2], v[3]);
        }
    } else {
        float s = 0.f;
#pragma unroll
        for (int j = 0; j < 4; j++) {
            const int n = nB0 + j * 8;
            const int mm[4] = {mA, mA, mA + 8, mA + 8};
            const int nn[4] = {n, n + 1, n, n + 1};
#pragma unroll
            for (int c = 0; c < 4; c++) {
                float v = acc[j][c] + bias[nn[c]];
                if (EPI == EPI_KLD) {
                    float pr = 0.1f * tanhf(v);
                    float e = (pr - aux2[(size_t)mm[c] * ZZ + nn[c]]) /
                              aux3[(size_t)(mm[c] >> 3) * ZZ + nn[c]];
                    s += e * e;
                } else { // EPI_RECON
                    float d = aux[(size_t)(mm[c] >> 3) * DD + nn[c]] - v;
                    float nll = 0.5f * (LOG2PI_C + d * d);
                    s += nll * aux2[mm[c] >> 3];
                }
            }
        }
        __shared__ float red[256];
        red[tid] = s;
        __syncthreads();
        for (int o = 128; o > 0; o >>= 1) {
            if (tid < o) red[tid] += red[tid + o];
            __syncthreads();
        }
        if (tid == 0) part[blockIdx.y * gridDim.x + blockIdx.x] = red[0];
    }
}

// ---------------- persistent scan kernel (unchanged, fp32) ----------------
#define SMEM_SCAN ((256*36 + 256*68 + 16*132 + 16*68) * 4)

__device__ __forceinline__ void gridbar(unsigned& tgt)
{
    __syncthreads();
    if (threadIdx.x == 0) {
        __threadfence();
        atomicAdd(&g_barcnt, 1u);
        tgt += SCAN_BLOCKS;
        while (*(volatile unsigned*)&g_barcnt < tgt) { }
        __threadfence();
    }
    __syncthreads();
}

__global__ void __launch_bounds__(SCAN_THREADS, 1) scan_kernel(
    const float* __restrict__ w1z,      // drift_w1 + RR*HH
    const float* __restrict__ w2,       // drift_w2
    const float* __restrict__ b2,       // drift_b2
    const float* __restrict__ noise)
{
    extern __shared__ float sm[];
    float* W1s = sm;                       // [256][36]
    float* W2s = sm + 256*36;              // [256][68]
    float* As  = sm + 256*36 + 256*68;     // [16][132]
    float* As2 = As + 16*132;              // [16][68]

    const int tid = threadIdx.x;
    const int bid = blockIdx.x;

    const int bmA = bid >> 5;
    const int bnA = bid & 31;
    const int tyA = tid >> 3;
    const int txA = tid & 7;

    const int kcB = bid & 3;
    const int moB = (bid >> 2) >> 2;
    const int noB = (bid >> 2) & 3;
    const int tyB = tid >> 4;
    const int txB = tid & 15;

    for (int i = tid; i < 256*32; i += SCAN_THREADS) {
        int k = i >> 5, c = i & 31;
        W1s[k*36 + c] = w1z[(size_t)k*HH + bnA*32 + c];
    }
    for (int i = tid; i < 256*64; i += SCAN_THREADS) {
        int k = i >> 6, c = i & 63;
        W2s[k*68 + c] = w2[(size_t)(kcB*256 + k)*ZZ + noB*64 + c];
    }
    __syncthreads();

    unsigned tgt = 0;
    const int wid = tid >> 5, lane = tid & 31;

    for (int t = 0; t < TT; t++) {
        const float* z = g_states + (size_t)t*BSZ*ZZ;
        float* zwt = g_zw + (size_t)t*BSZ*HH;
        {
            float acc[4][4];
#pragma unroll
            for (int i = 0; i < 4; i++)
#pragma unroll
                for (int j = 0; j < 4; j++) acc[i][j] = 0.f;

            for (int k0 = 0; k0 < ZZ; k0 += 16) {
#pragma unroll
                for (int r = 0; r < 2; r++) {
                    int v = tid + SCAN_THREADS*r;
                    int row = v >> 2, kq = (v & 3) << 2;
                    float4 f = *(const float4*)&z[(size_t)(bmA*128 + row)*ZZ + k0 + kq];
                    As[(kq+0)*132 + row] = f.x;
                    As[(kq+1)*132 + row] = f.y;
                    As[(kq+2)*132 + row] = f.z;
                    As[(kq+3)*132 + row] = f.w;
                }
                __syncthreads();
#pragma unroll
                for (int kk = 0; kk < 16; kk++) {
                    float4 a = *(float4*)&As[kk*132 + tyA*4];
                    float4 b = *(float4*)&W1s[(k0+kk)*36 + txA*4];
                    acc[0][0] += a.x*b.x; acc[0][1] += a.x*b.y; acc[0][2] += a.x*b.z; acc[0][3] += a.x*b.w;
                    acc[1][0] += a.y*b.x; acc[1][1] += a.y*b.y; acc[1][2] += a.y*b.z; acc[1][3] += a.y*b.w;
                    acc[2][0] += a.z*b.x; acc[2][1] += a.z*b.y; acc[2][2] += a.z*b.z; acc[2][3] += a.z*b.w;
                    acc[3][0] += a.w*b.x; acc[3][1] += a.w*b.y; acc[3][2] += a.w*b.z; acc[3][3] += a.w*b.w;
                }
                __syncthreads();
            }
#pragma unroll
            for (int i = 0; i < 4; i++) {
                float4 o = make_float4(acc[i][0], acc[i][1], acc[i][2], acc[i][3]);
                *(float4*)&zwt[(size_t)(bmA*128 + tyA*4 + i)*HH + bnA*32 + txA*4] = o;
            }
        }
        gridbar(tgt);

        {
            const float* hp = g_hpost + (size_t)t*BB*HH;
            float acc[4][4];
#pragma unroll
            for (int i = 0; i < 4; i++)
#pragma unroll
                for (int j = 0; j < 4; j++) acc[i][j] = 0.f;

            for (int k0 = 0; k0 < 256; k0 += 16) {
                {
                    int row = tid >> 2, kq = (tid & 3) << 2;
                    int gk = kcB*256 + k0 + kq;
                    float4 f = *(const float4*)&zwt[(size_t)(moB*64 + row)*HH + gk];
                    float4 h = *(const float4*)&hp[(size_t)((moB*64 + row) >> 3)*HH + gk];
                    As2[(kq+0)*68 + row] = fmaxf(f.x + h.x, 0.f);
                    As2[(kq+1)*68 + row] = fmaxf(f.y + h.y, 0.f);
                    As2[(kq+2)*68 + row] = fmaxf(f.z + h.z, 0.f);
                    As2[(kq+3)*68 + row] = fmaxf(f.w + h.w, 0.f);
                }
                __syncthreads();
#pragma unroll
                for (int kk = 0; kk < 16; kk++) {
                    float4 a = *(float4*)&As2[kk*68 + tyB*4];
                    float4 b = *(float4*)&W2s[(k0+kk)*68 + txB*4];
                    acc[0][0] += a.x*b.x; acc[0][1] += a.x*b.y; acc[0][2] += a.x*b.z; acc[0][3] += a.x*b.w;
                    acc[1][0] += a.y*b.x; acc[1][1] += a.y*b.y; acc[1][2] += a.y*b.z; acc[1][3] += a.y*b.w;
                    acc[2][0] += a.z*b.x; acc[2][1] += a.z*b.y; acc[2][2] += a.z*b.z; acc[2][3] += a.z*b.w;
                    acc[3][0] += a.w*b.x; acc[3][1] += a.w*b.y; acc[3][2] += a.w*b.z; acc[3][3] += a.w*b.w;
                }
                __syncthreads();
            }
            float* gp = g_part + (size_t)kcB*BSZ*ZZ;
#pragma unroll
            for (int i = 0; i < 4; i++) {
                float4 o = make_float4(acc[i][0], acc[i][1], acc[i][2], acc[i][3]);
                *(float4*)&gp[(size_t)(moB*64 + tyB*4 + i)*ZZ + noB*64 + txB*4] = o;
            }
        }
        gridbar(tgt);

        if (wid < 4) {
            const int row = bid*4 + wid;
            const float* zr = g_states + (size_t)t*BSZ*ZZ + (size_t)row*ZZ;
            const float* nr = noise + (size_t)t*BSZ*ZZ + (size_t)row*ZZ;
            const float* dr = g_diff + ((size_t)t*BB + (row >> 3))*ZZ;
            float* pr = g_post + (size_t)t*BSZ*ZZ + (size_t)row*ZZ;
            float* outz = g_states + (size_t)(t+1)*BSZ*ZZ + (size_t)row*ZZ;

            float v8[8];
            float vmin = 3.4e38f, vmax = -3.4e38f;
#pragma unroll
            for (int j = 0; j < 2; j++) {
                const int cb = lane*4 + 128*j;
                float4 s  = *(const float4*)&g_part[0*BSZ*ZZ + (size_t)row*ZZ + cb];
                float4 s1 = *(const float4*)&g_part[1*BSZ*ZZ + (size_t)row*ZZ + cb];
                float4 s2 = *(const float4*)&g_part[2*BSZ*ZZ + (size_t)row*ZZ + cb];
                float4 s3 = *(const float4*)&g_part[3*BSZ*ZZ + (size_t)row*ZZ + cb];
                float4 bb = *(const float4*)&b2[cb];
                float4 zv = *(const float4*)&zr[cb];
                float4 nv = *(const float4*)&nr[cb];
                float4 dv = *(const float4*)&dr[cb];
                float pd0 = 0.1f * tanhf(s.x + s1.x + s2.x + s3.x + bb.x);
                float pd1 = 0.1f * tanhf(s.y + s1.y + s2.y + s3.y + bb.y);
                float pd2 = 0.1f * tanhf(s.z + s1.z + s2.z + s3.z + bb.z);
                float pd3 = 0.1f * tanhf(s.w + s1.w + s2.w + s3.w + bb.w);
                *(float4*)&pr[cb] = make_float4(pd0, pd1, pd2, pd3);
                float n0v = zv.x + DT_C*pd0 + SQRT_DT_C*dv.x*nv.x;
                float n1v = zv.y + DT_C*pd1 + SQRT_DT_C*dv.y*nv.y;
                float n2v = zv.z + DT_C*pd2 + SQRT_DT_C*dv.z*nv.z;
                float n3v = zv.w + DT_C*pd3 + SQRT_DT_C*dv.w*nv.w;
                v8[j*4+0] = n0v; v8[j*4+1] = n1v; v8[j*4+2] = n2v; v8[j*4+3] = n3v;
                vmin = fminf(vmin, fminf(fminf(n0v, n1v), fminf(n2v, n3v)));
                vmax = fmaxf(vmax, fmaxf(fmaxf(n0v, n1v), fmaxf(n2v, n3v)));
            }
#pragma unroll
            for (int o = 16; o > 0; o >>= 1) {
                vmin = fminf(vmin, __shfl_xor_sync(0xffffffffu, vmin, o));
                vmax = fmaxf(vmax, __shfl_xor_sync(0xffffffffu, vmax, o));
            }
            const float inv = 1.f / (vmax - vmin);
#pragma unroll
            for (int j = 0; j < 2; j++) {
                const int cb = lane*4 + 128*j;
                *(float4*)&outz[cb] = make_float4((v8[j*4+0]-vmin)*inv, (v8[j*4+1]-vmin)*inv,
                                                  (v8[j*4+2]-vmin)*inv, (v8[j*4+3]-vmin)*inv);
            }
        }
        gridbar(tgt);
    }
}

// ---------------- small kernels ----------------
__global__ void reset_kernel() { g_barcnt = 0u; }

__global__ void mt_kernel(const float* __restrict__ M)
{
    int r = blockIdx.x * blockDim.x + threadIdx.x;
    if (r < TT * BB) {
        const float* p = M + (size_t)r * DD;
        float s = 0.f;
        for (int d = 0; d < DD; d++) s += p[d];
        g_Mt[r] = s * (1.f / DD);
    }
}

__global__ void z0_kernel(const float* __restrict__ cov,
                          const float* __restrict__ w1, const float* __restrict__ b1,
                          const float* __restrict__ w2, const float* __restrict__ b2)
{
    int b = blockIdx.x;
    __shared__ float cv[16];
    __shared__ float hid[64];
    if (threadIdx.x < 16) cv[threadIdx.x] = cov[b * 16 + threadIdx.x];
    __syncthreads();
    if (threadIdx.x < 64) {
        float s = b1[threadIdx.x];
        for (int i = 0; i < 16; i++) s += cv[i] * w1[i * 64 + threadIdx.x];
        hid[threadIdx.x] = fmaxf(s, 0.f);
    }
    __syncthreads();
    int n = threadIdx.x;
    float s = b2[n];
    for (int j = 0; j < 64; j++) s += hid[j] * w2[j * 256 + n];
    float z = tanhf(s);
    for (int ss = 0; ss < SS; ss++)
        g_states[(size_t)(b * SS + ss) * ZZ + n] = z;
}

__global__ void out_copy_kernel(float* __restrict__ out)
{
    int i = blockIdx.x * 256 + threadIdx.x;
    out[i] = g_states[(size_t)TT * BSZ * ZZ + i];
}

__global__ void scal_kernel(float* __restrict__ out)
{
    __shared__ float red[256];
    int tid = threadIdx.x;
    float s = 0.f;
    for (int i = tid; i < KLD_PARTS; i += 256) s += g_kld_part[i];
    red[tid] = s;
    __syncthreads();
    for (int o = 128; o > 0; o >>= 1) { if (tid < o) red[tid] += red[tid + o]; __syncthreads(); }
    float kldsum = red[0];
    __syncthreads();
    s = 0.f;
    for (int i = tid; i < RECON_PARTS; i += 256) s += g_recon_part[i];
    red[tid] = s;
    __syncthreads();
    for (int o = 128; o > 0; o >>= 1) { if (tid < o) red[tid] += red[tid + o]; __syncthreads(); }
    if (tid == 0) {
        float reconsum = red[0];
        float lk = (0.5f * DT_C / (float)(BB * SS)) * kldsum;
        float lr = reconsum * (1.f / (float)(BB * SS));
        out[131072] = lr + lk;   // loss_total
        out[131073] = lr;        // loss_recon
        out[131074] = lk;        // loss_kld
    }
}

// ---------------- launch ----------------
extern "C" void kernel_launch(void* const* d_in, const int* in_sizes, int n_in,
                              void* d_out, int out_size)
{
    (void)in_sizes; (void)n_in; (void)out_size;
    const float* X        = (const float*)d_in[0];
    const float* M        = (const float*)d_in[1];
    const float* cov      = (const float*)d_in[2];
    const float* path_h   = (const float*)d_in[3];
    const float* path_hpos= (const float*)d_in[4];
    const float* noise    = (const float*)d_in[5];
    const float* drift_w1 = (const float*)d_in[6];
    const float* drift_b1 = (const float*)d_in[7];
    const float* drift_w2 = (const float*)d_in[8];
    const float* drift_b2 = (const float*)d_in[9];
    const float* diff_w1  = (const float*)d_in[10];
    const float* diff_b1  = (const float*)d_in[11];
    const float* diff_w2  = (const float*)d_in[12];
    const float* diff_b2  = (const float*)d_in[13];
    const float* p_w1     = (const float*)d_in[14];
    const float* p_b1     = (const float*)d_in[15];
    const float* p_w2     = (const float*)d_in[16];
    const float* p_b2     = (const float*)d_in[17];
    const float* cov_w1   = (const float*)d_in[18];
    const float* cov_b1   = (const float*)d_in[19];
    const float* cov_w2   = (const float*)d_in[20];
    const float* cov_b2   = (const float*)d_in[21];
    float* out = (float*)d_out;

    float *hprior, *hpost, *ppart, *dtmp, *diffp, *states, *zw, *post, *A3, *kldp, *reconp, *Mtp;
    cudaGetSymbolAddress((void**)&hprior, g_hprior);
    cudaGetSymbolAddress((void**)&hpost,  g_hpost);
    cudaGetSymbolAddress((void**)&ppart,  g_ppart);
    cudaGetSymbolAddress((void**)&dtmp,   g_dtmp);
    cudaGetSymbolAddress((void**)&diffp,  g_diff);
    cudaGetSymbolAddress((void**)&states, g_states);
    cudaGetSymbolAddress((void**)&zw,     g_zw);
    cudaGetSymbolAddress((void**)&post,   g_post);
    cudaGetSymbolAddress((void**)&A3,     g_A3);
    cudaGetSymbolAddress((void**)&kldp,   g_kld_part);
    cudaGetSymbolAddress((void**)&reconp, g_recon_part);
    cudaGetSymbolAddress((void**)&Mtp,    g_Mt);

    static int smem_set = 0;
    if (!smem_set) {
        cudaFuncSetAttribute(scan_kernel,
                             cudaFuncAttributeMaxDynamicSharedMemorySize, SMEM_SCAN);
        smem_set = 1;
    }

    // ---- precompute (parallel over T) ----
    reset_kernel<<<1, 1>>>();
    gemm_t<PRO_PLAIN, EPI_STORE><<<dim3(16, 200), 256>>>(
        path_h, RR, drift_w1, HH, hprior, HH, RR, drift_b1,
        nullptr, nullptr, nullptr, nullptr);
    gemm_t<PRO_PLAIN, EPI_STORE><<<dim3(16, 200), 256>>>(
        path_hpos, RR, drift_w1, HH, hpost, HH, RR, drift_b1,
        nullptr, nullptr, nullptr, nullptr);
    gemm_t<PRO_PLAIN, EPI_STORE><<<dim3(16, 200), 256>>>(
        path_h, RR, p_w1, HH, ppart, HH, RR, p_b1,
        nullptr, nullptr, nullptr, nullptr);
    gemm_t<PRO_PLAIN, EPI_RELU><<<dim3(16, 200), 256>>>(
        path_h, RR, diff_w1, HH, dtmp, HH, RR, diff_b1,
        nullptr, nullptr, nullptr, nullptr);
    gemm_t<PRO_PLAIN, EPI_EXP><<<dim3(4, 200), 256>>>(
        dtmp, HH, diff_w2, ZZ, diffp, ZZ, HH, diff_b2,
        nullptr, nullptr, nullptr, nullptr);
    mt_kernel<<<(TT * BB + 255) / 256, 256>>>(M);
    z0_kernel<<<BB, 256>>>(cov, cov_w1, cov_b1, cov_w2, cov_b2);

    // ---- sequential scan: ONE persistent kernel for all 200 steps ----
    scan_kernel<<<SCAN_BLOCKS, SCAN_THREADS, SMEM_SCAN>>>(
        drift_w1 + (size_t)RR * HH, drift_w2, drift_b2, noise);

    // ---- batch epilogue (parallel over all T) ----
    gemm_t<PRO_ADDRELU, EPI_KLD><<<dim3(4, 1600), 256>>>(
        zw, HH, drift_w2, ZZ, nullptr, 0, HH, drift_b2,
        hprior, post, diffp, kldp);
    gemm_t<PRO_PLAIN, EPI_BCASTRELU><<<dim3(16, 1600), 256>>>(
        states + (size_t)BSZ * ZZ, ZZ, p_w1 + (size_t)RR * HH, HH,
        A3, HH, ZZ, nullptr, ppart, nullptr, nullptr, nullptr);
    gemm_t<PRO_PLAIN, EPI_RECON><<<dim3(2, 1600), 256>>>(
        A3, HH, p_w2, DD, nullptr, 0, HH, p_b2,
        X, Mtp, nullptr, reconp);

    // ---- output: z_final then (total, recon, kld) ----
    out_copy_kernel<<<512, 256>>>(out);
    scal_kernel<<<1, 256>>>(out);
}

// round 6
// speedup vs baseline: 3.4013x; 1.3573x over previous
#include <cuda_runtime.h>
#include <math.h>
#include <stdint.h>

#define TT 200
#define BB 64
#define SS 8
#define DD 128
#define RR 512
#define ZZ 256
#define HH 1024
#define BSZ (BB*SS)            /* 512 rows per step */
#define DT_C 0.05f
#define SQRT_DT_C 0.223606797749979f
#define LOG2PI_C 1.8378770664093453f

#define KLD_PARTS  (1600*4)
#define RECON_PARTS (1600*2)

#define SCAN_BLOCKS 128
#define SCAN_THREADS 256

// ---------------- device scratch (static, allocation-free) ----------------
__device__ float g_hprior[TT*BB*HH];        // h@drift_w1[:R] + b1
__device__ float g_hpost [TT*BB*HH];        // hpos@drift_w1[:R] + b1
__device__ float g_ppart [TT*BB*HH];        // h@p_w1[:R] + p_b1
__device__ float g_dtmp  [TT*BB*HH];        // relu(h@diff_w1+b1)
__device__ float g_diff  [TT*BB*ZZ];        // exp(diff MLP)
__device__ float g_Mt    [TT*BB];
__device__ float g_states[(TT+1)*BSZ*ZZ];   // z trajectory (normalized)
__device__ float g_zw    [TT*BSZ*HH];       // z_t @ drift_w1[R:]
__device__ float g_post  [TT*BSZ*ZZ];       // posterior drift
__device__ float g_A3    [TT*BSZ*HH];       // decoder hidden
__device__ float g_part  [4*BSZ*ZZ];        // split-K partials for scan
__device__ float g_kld_part[KLD_PARTS];
__device__ float g_recon_part[RECON_PARTS];
__device__ unsigned g_barcnt;

// ---------------- tf32 helpers ----------------
__device__ __forceinline__ uint32_t f2tf(float f)
{
    uint32_t u;
    asm("cvt.rna.tf32.f32 %0, %1;" : "=r"(u) : "f"(f));
    return u;
}

__device__ __forceinline__ void mma8(float* c,
    uint32_t a0, uint32_t a1, uint32_t a2, uint32_t a3,
    uint32_t b0, uint32_t b1)
{
    asm("mma.sync.aligned.m16n8k8.row.col.f32.tf32.tf32.f32 "
        "{%0,%1,%2,%3},{%4,%5,%6,%7},{%8,%9},{%0,%1,%2,%3};"
        : "+f"(c[0]), "+f"(c[1]), "+f"(c[2]), "+f"(c[3])
        : "r"(a0), "r"(a1), "r"(a2), "r"(a3), "r"(b0), "r"(b1));
}

// ---------------- generic 64x64 tf32 GEMM with fused pro/epilogues ------
#define PRO_PLAIN 0
#define PRO_ADDRELU 1      // A := relu(A + aux[(m>>3)*H + k])
#define EPI_STORE 0        // C = acc (+bias)
#define EPI_RELU  1
#define EPI_EXP   2
#define EPI_BCASTRELU 3    // C = relu(acc + aux[(m>>3)*H + n])
#define EPI_KLD   4        // reduce ((0.1 tanh(acc+b)-post)/diff)^2
#define EPI_RECON 5        // reduce 0.5(log2pi+(X-(acc+b))^2)*Mt

template<int PRO, int EPI>
__global__ void __launch_bounds__(256) gemm_t(
    const float* __restrict__ A, int lda,
    const float* __restrict__ Bm, int ldb,
    float* __restrict__ C, int ldc, int K,
    const float* __restrict__ bias,
    const float* __restrict__ aux,
    const float* __restrict__ aux2,
    const float* __restrict__ aux3,
    float* __restrict__ part)
{
    __shared__ uint32_t As[64][20];   // stride 20 -> conflict-free frag loads
    __shared__ uint32_t Bs[16][72];   // stride 72 -> conflict-free frag loads
    const int tid = threadIdx.x;
    const int m0 = blockIdx.y * 64, n0 = blockIdx.x * 64;
    const int wid = tid >> 5, lane = tid & 31;
    const int wm = (wid & 3) * 16;     // warp row offset in tile
    const int wn = (wid >> 2) * 32;    // warp col offset in tile
    const int qr = lane >> 2;          // 0..7
    const int qc = lane & 3;           // 0..3
    const int arow = tid >> 2;         // 0..63
    const int ak4  = (tid & 3) << 2;   // 0,4,8,12
    const int brow = tid >> 4;         // 0..15
    const int bn4  = (tid & 15) << 2;

    float acc[4][4];
#pragma unroll
    for (int j = 0; j < 4; j++)
#pragma unroll
        for (int c = 0; c < 4; c++) acc[j][c] = 0.f;

    for (int k0 = 0; k0 < K; k0 += 16) {
        float4 av = *(const float4*)&A[(size_t)(m0 + arow) * lda + k0 + ak4];
        if (PRO == PRO_ADDRELU) {
            const float4 hv = *(const float4*)&aux[(size_t)((m0 + arow) >> 3) * HH + k0 + ak4];
            av.x = fmaxf(av.x + hv.x, 0.f); av.y = fmaxf(av.y + hv.y, 0.f);
            av.z = fmaxf(av.z + hv.z, 0.f); av.w = fmaxf(av.w + hv.w, 0.f);
        }
        {
            uint4 t;
            t.x = f2tf(av.x); t.y = f2tf(av.y); t.z = f2tf(av.z); t.w = f2tf(av.w);
            *(uint4*)&As[arow][ak4] = t;
        }
        {
            float4 bv = *(const float4*)&Bm[(size_t)(k0 + brow) * ldb + n0 + bn4];
            uint4 t;
            t.x = f2tf(bv.x); t.y = f2tf(bv.y); t.z = f2tf(bv.z); t.w = f2tf(bv.w);
            *(uint4*)&Bs[brow][bn4] = t;
        }
        __syncthreads();
#pragma unroll
        for (int kk = 0; kk < 16; kk += 8) {
            uint32_t a0 = As[wm + qr    ][kk + qc];
            uint32_t a1 = As[wm + qr + 8][kk + qc];
            uint32_t a2 = As[wm + qr    ][kk + qc + 4];
            uint32_t a3 = As[wm + qr + 8][kk + qc + 4];
#pragma unroll
            for (int j = 0; j < 4; j++) {
                const int cn = wn + j * 8 + qr;
                mma8(acc[j], a0, a1, a2, a3, Bs[kk + qc][cn], Bs[kk + qc + 4][cn]);
            }
        }
        __syncthreads();
    }

    const int mA = m0 + wm + qr;
    const int nB0 = n0 + wn + qc * 2;

    if (EPI <= 3) {
        const bool hasb = (bias != nullptr);
#pragma unroll
        for (int j = 0; j < 4; j++) {
            const int n = nB0 + j * 8;
            float v[4] = {acc[j][0], acc[j][1], acc[j][2], acc[j][3]};
            const int mm[4] = {mA, mA, mA + 8, mA + 8};
            const int nn[4] = {n, n + 1, n, n + 1};
#pragma unroll
            for (int c = 0; c < 4; c++) {
                if (hasb) v[c] += bias[nn[c]];
                if (EPI == EPI_RELU) v[c] = fmaxf(v[c], 0.f);
                if (EPI == EPI_EXP)  v[c] = expf(v[c]);
                if (EPI == EPI_BCASTRELU)
                    v[c] = fmaxf(v[c] + aux[(size_t)(mm[c] >> 3) * HH + nn[c]], 0.f);
            }
            *(float2*)&C[(size_t)mA * ldc + n]       = make_float2(v[0], v[1]);
            *(float2*)&C[(size_t)(mA + 8) * ldc + n] = make_float2(v[2], v[3]);
        }
    } else {
        float s = 0.f;
#pragma unroll
        for (int j = 0; j < 4; j++) {
            const int n = nB0 + j * 8;
            const int mm[4] = {mA, mA, mA + 8, mA + 8};
            const int nn[4] = {n, n + 1, n, n + 1};
#pragma unroll
            for (int c = 0; c < 4; c++) {
                float v = acc[j][c] + bias[nn[c]];
                if (EPI == EPI_KLD) {
                    float pr = 0.1f * tanhf(v);
                    float e = (pr - aux2[(size_t)mm[c] * ZZ + nn[c]]) /
                              aux3[(size_t)(mm[c] >> 3) * ZZ + nn[c]];
                    s += e * e;
                } else { // EPI_RECON
                    float d = aux[(size_t)(mm[c] >> 3) * DD + nn[c]] - v;
                    float nll = 0.5f * (LOG2PI_C + d * d);
                    s += nll * aux2[mm[c] >> 3];
                }
            }
        }
        __shared__ float red[256];
        red[tid] = s;
        __syncthreads();
        for (int o = 128; o > 0; o >>= 1) {
            if (tid < o) red[tid] += red[tid + o];
            __syncthreads();
        }
        if (tid == 0) part[blockIdx.y * gridDim.x + blockIdx.x] = red[0];
    }
}

// ---------------- persistent scan kernel (tf32 tensorized) ----------------
//   W1s: tf32 [256][36]  = 36864 B   (persistent, conflict-free: 36%32=4)
//   W2s: tf32 [256][68]  = 69632 B   (persistent, 68%32=4)
//   St : tf32 stage [128][36] = 18432 B (A: 128x32 z; B1: 64x32 hidden)
#define SMEM_SCAN ((256*36 + 256*68 + 128*36) * 4)

__device__ __forceinline__ void gridbar(unsigned& tgt)
{
    __syncthreads();
    if (threadIdx.x == 0) {
        __threadfence();
        atomicAdd(&g_barcnt, 1u);
        tgt += SCAN_BLOCKS;
        while (*(volatile unsigned*)&g_barcnt < tgt) { }
        __threadfence();
    }
    __syncthreads();
}

__global__ void __launch_bounds__(SCAN_THREADS, 1) scan_kernel(
    const float* __restrict__ w1z,      // drift_w1 + RR*HH
    const float* __restrict__ w2,       // drift_w2
    const float* __restrict__ b2,       // drift_b2
    const float* __restrict__ noise)
{
    extern __shared__ uint32_t smu[];
    uint32_t* W1s = smu;                     // [256][36]
    uint32_t* W2s = smu + 256*36;            // [256][68]
    uint32_t* St  = smu + 256*36 + 256*68;   // [128][36]

    const int tid = threadIdx.x;
    const int bid = blockIdx.x;
    const int wid = tid >> 5, lane = tid & 31;
    const int qr = lane >> 2;   // 0..7
    const int qc = lane & 3;    // 0..3

    // phase A geometry: 4 m-tiles (128 rows) x 32 n-slices (32 cols of 1024)
    const int bmA = bid >> 5;
    const int bnA = bid & 31;
    const int wmA = wid * 16;          // 8 warps x 16 rows

    // phase B1 geometry: 8 m-tiles(64r) x 4 n-tiles(64c) x 4 k-chunks(256)
    const int kcB = bid & 3;
    const int moB = (bid >> 2) >> 2;   // 0..7
    const int noB = (bid >> 2) & 3;    // 0..3
    const int wrB = (wid & 3) * 16;    // warp rows
    const int wcB = (wid >> 2) * 32;   // warp cols

    // load persistent weight slices (converted to tf32 once)
    for (int i = tid; i < 256*32; i += SCAN_THREADS) {
        int k = i >> 5, c = i & 31;
        W1s[k*36 + c] = f2tf(w1z[(size_t)k*HH + bnA*32 + c]);
    }
    for (int i = tid; i < 256*64; i += SCAN_THREADS) {
        int k = i >> 6, c = i & 63;
        W2s[k*68 + c] = f2tf(w2[(size_t)(kcB*256 + k)*ZZ + noB*64 + c]);
    }
    __syncthreads();

    unsigned tgt = 0;

    for (int t = 0; t < TT; t++) {
        const float* z = g_states + (size_t)t*BSZ*ZZ;
        float* zwt = g_zw + (size_t)t*BSZ*HH;

        // ============ phase A: zw[t] = z_t @ w1z (tf32 mma) ============
        {
            float acc[4][4];
#pragma unroll
            for (int j = 0; j < 4; j++)
#pragma unroll
                for (int c = 0; c < 4; c++) acc[j][c] = 0.f;

            for (int kc = 0; kc < 8; kc++) {
                // stage 128x32 z chunk as tf32
#pragma unroll
                for (int i = 0; i < 4; i++) {
                    int idx = tid + SCAN_THREADS*i;   // 0..1023
                    int row = idx >> 3, q = idx & 7;
                    float4 f = *(const float4*)&z[(size_t)(bmA*128 + row)*ZZ + kc*32 + q*4];
                    uint4 u;
                    u.x = f2tf(f.x); u.y = f2tf(f.y); u.z = f2tf(f.z); u.w = f2tf(f.w);
                    *(uint4*)&St[row*36 + q*4] = u;
                }
                __syncthreads();
#pragma unroll
                for (int k8 = 0; k8 < 4; k8++) {
                    const int kk = k8*8;
                    uint32_t a0 = St[(wmA + qr    )*36 + kk + qc];
                    uint32_t a1 = St[(wmA + qr + 8)*36 + kk + qc];
                    uint32_t a2 = St[(wmA + qr    )*36 + kk + qc + 4];
                    uint32_t a3 = St[(wmA + qr + 8)*36 + kk + qc + 4];
#pragma unroll
                    for (int j = 0; j < 4; j++) {
                        const int n = j*8 + qr;
                        mma8(acc[j], a0, a1, a2, a3,
                             W1s[(kc*32 + kk + qc    )*36 + n],
                             W1s[(kc*32 + kk + qc + 4)*36 + n]);
                    }
                }
                __syncthreads();
            }
            const int mA = bmA*128 + wmA + qr;
#pragma unroll
            for (int j = 0; j < 4; j++) {
                const int n = bnA*32 + j*8 + qc*2;
                *(float2*)&zwt[(size_t)mA*HH + n]       = make_float2(acc[j][0], acc[j][1]);
                *(float2*)&zwt[(size_t)(mA+8)*HH + n]   = make_float2(acc[j][2], acc[j][3]);
            }
        }
        gridbar(tgt);

        // ============ phase B1: partial relu(zw+hpost)@W2 (tf32 mma) ============
        {
            const float* hp = g_hpost + (size_t)t*BB*HH;
            float acc[4][4];
#pragma unroll
            for (int j = 0; j < 4; j++)
#pragma unroll
                for (int c = 0; c < 4; c++) acc[j][c] = 0.f;

            for (int kc = 0; kc < 8; kc++) {
                // stage 64x32 hidden chunk (relu(zw+hpost)) as tf32
#pragma unroll
                for (int i = 0; i < 2; i++) {
                    int idx = tid + SCAN_THREADS*i;   // 0..511
                    int row = idx >> 3, q = idx & 7;
                    int gk = kcB*256 + kc*32 + q*4;
                    float4 f = *(const float4*)&zwt[(size_t)(moB*64 + row)*HH + gk];
                    float4 h = *(const float4*)&hp[(size_t)((moB*64 + row) >> 3)*HH + gk];
                    uint4 u;
                    u.x = f2tf(fmaxf(f.x + h.x, 0.f));
                    u.y = f2tf(fmaxf(f.y + h.y, 0.f));
                    u.z = f2tf(fmaxf(f.z + h.z, 0.f));
                    u.w = f2tf(fmaxf(f.w + h.w, 0.f));
                    *(uint4*)&St[row*36 + q*4] = u;
                }
                __syncthreads();
#pragma unroll
                for (int k8 = 0; k8 < 4; k8++) {
                    const int kk = k8*8;
                    uint32_t a0 = St[(wrB + qr    )*36 + kk + qc];
                    uint32_t a1 = St[(wrB + qr + 8)*36 + kk + qc];
                    uint32_t a2 = St[(wrB + qr    )*36 + kk + qc + 4];
                    uint32_t a3 = St[(wrB + qr + 8)*36 + kk + qc + 4];
#pragma unroll
                    for (int j = 0; j < 4; j++) {
                        const int n = wcB + j*8 + qr;
                        mma8(acc[j], a0, a1, a2, a3,
                             W2s[(kc*32 + kk + qc    )*68 + n],
                             W2s[(kc*32 + kk + qc + 4)*68 + n]);
                    }
                }
                __syncthreads();
            }
            float* gp = g_part + (size_t)kcB*BSZ*ZZ;
            const int mB = moB*64 + wrB + qr;
#pragma unroll
            for (int j = 0; j < 4; j++) {
                const int n = noB*64 + wcB + j*8 + qc*2;
                *(float2*)&gp[(size_t)mB*ZZ + n]       = make_float2(acc[j][0], acc[j][1]);
                *(float2*)&gp[(size_t)(mB+8)*ZZ + n]   = make_float2(acc[j][2], acc[j][3]);
            }
        }
        gridbar(tgt);

        // ============ phase B2: combine + tanh + Euler + row minmax (fp32) ============
        if (wid < 4) {
            const int row = bid*4 + wid;
            const float* zr = g_states + (size_t)t*BSZ*ZZ + (size_t)row*ZZ;
            const float* nr = noise + (size_t)t*BSZ*ZZ + (size_t)row*ZZ;
            const float* dr = g_diff + ((size_t)t*BB + (row >> 3))*ZZ;
            float* pr = g_post + (size_t)t*BSZ*ZZ + (size_t)row*ZZ;
            float* outz = g_states + (size_t)(t+1)*BSZ*ZZ + (size_t)row*ZZ;

            float v8[8];
            float vmin = 3.4e38f, vmax = -3.4e38f;
#pragma unroll
            for (int j = 0; j < 2; j++) {
                const int cb = lane*4 + 128*j;
                float4 s  = *(const float4*)&g_part[0*BSZ*ZZ + (size_t)row*ZZ + cb];
                float4 s1 = *(const float4*)&g_part[1*BSZ*ZZ + (size_t)row*ZZ + cb];
                float4 s2 = *(const float4*)&g_part[2*BSZ*ZZ + (size_t)row*ZZ + cb];
                float4 s3 = *(const float4*)&g_part[3*BSZ*ZZ + (size_t)row*ZZ + cb];
                float4 bb = *(const float4*)&b2[cb];
                float4 zv = *(const float4*)&zr[cb];
                float4 nv = *(const float4*)&nr[cb];
                float4 dv = *(const float4*)&dr[cb];
                float pd0 = 0.1f * tanhf(s.x + s1.x + s2.x + s3.x + bb.x);
                float pd1 = 0.1f * tanhf(s.y + s1.y + s2.y + s3.y + bb.y);
                float pd2 = 0.1f * tanhf(s.z + s1.z + s2.z + s3.z + bb.z);
                float pd3 = 0.1f * tanhf(s.w + s1.w + s2.w + s3.w + bb.w);
                *(float4*)&pr[cb] = make_float4(pd0, pd1, pd2, pd3);
                float n0v = zv.x + DT_C*pd0 + SQRT_DT_C*dv.x*nv.x;
                float n1v = zv.y + DT_C*pd1 + SQRT_DT_C*dv.y*nv.y;
                float n2v = zv.z + DT_C*pd2 + SQRT_DT_C*dv.z*nv.z;
                float n3v = zv.w + DT_C*pd3 + SQRT_DT_C*dv.w*nv.w;
                v8[j*4+0] = n0v; v8[j*4+1] = n1v; v8[j*4+2] = n2v; v8[j*4+3] = n3v;
                vmin = fminf(vmin, fminf(fminf(n0v, n1v), fminf(n2v, n3v)));
                vmax = fmaxf(vmax, fmaxf(fmaxf(n0v, n1v), fmaxf(n2v, n3v)));
            }
#pragma unroll
            for (int o = 16; o > 0; o >>= 1) {
                vmin = fminf(vmin, __shfl_xor_sync(0xffffffffu, vmin, o));
                vmax = fmaxf(vmax, __shfl_xor_sync(0xffffffffu, vmax, o));
            }
            const float inv = 1.f / (vmax - vmin);
#pragma unroll
            for (int j = 0; j < 2; j++) {
                const int cb = lane*4 + 128*j;
                *(float4*)&outz[cb] = make_float4((v8[j*4+0]-vmin)*inv, (v8[j*4+1]-vmin)*inv,
                                                  (v8[j*4+2]-vmin)*inv, (v8[j*4+3]-vmin)*inv);
            }
        }
        gridbar(tgt);
    }
}

// ---------------- small kernels ----------------
__global__ void reset_kernel() { g_barcnt = 0u; }

__global__ void mt_kernel(const float* __restrict__ M)
{
    int r = blockIdx.x * blockDim.x + threadIdx.x;
    if (r < TT * BB) {
        const float* p = M + (size_t)r * DD;
        float s = 0.f;
        for (int d = 0; d < DD; d++) s += p[d];
        g_Mt[r] = s * (1.f / DD);
    }
}

__global__ void z0_kernel(const float* __restrict__ cov,
                          const float* __restrict__ w1, const float* __restrict__ b1,
                          const float* __restrict__ w2, const float* __restrict__ b2)
{
    int b = blockIdx.x;
    __shared__ float cv[16];
    __shared__ float hid[64];
    if (threadIdx.x < 16) cv[threadIdx.x] = cov[b * 16 + threadIdx.x];
    __syncthreads();
    if (threadIdx.x < 64) {
        float s = b1[threadIdx.x];
        for (int i = 0; i < 16; i++) s += cv[i] * w1[i * 64 + threadIdx.x];
        hid[threadIdx.x] = fmaxf(s, 0.f);
    }
    __syncthreads();
    int n = threadIdx.x;
    float s = b2[n];
    for (int j = 0; j < 64; j++) s += hid[j] * w2[j * 256 + n];
    float z = tanhf(s);
    for (int ss = 0; ss < SS; ss++)
        g_states[(size_t)(b * SS + ss) * ZZ + n] = z;
}

__global__ void out_copy_kernel(float* __restrict__ out)
{
    int i = blockIdx.x * 256 + threadIdx.x;
    out[i] = g_states[(size_t)TT * BSZ * ZZ + i];
}

__global__ void scal_kernel(float* __restrict__ out)
{
    __shared__ float red[256];
    int tid = threadIdx.x;
    float s = 0.f;
    for (int i = tid; i < KLD_PARTS; i += 256) s += g_kld_part[i];
    red[tid] = s;
    __syncthreads();
    for (int o = 128; o > 0; o >>= 1) { if (tid < o) red[tid] += red[tid + o]; __syncthreads(); }
    float kldsum = red[0];
    __syncthreads();
    s = 0.f;
    for (int i = tid; i < RECON_PARTS; i += 256) s += g_recon_part[i];
    red[tid] = s;
    __syncthreads();
    for (int o = 128; o > 0; o >>= 1) { if (tid < o) red[tid] += red[tid + o]; __syncthreads(); }
    if (tid == 0) {
        float reconsum = red[0];
        float lk = (0.5f * DT_C / (float)(BB * SS)) * kldsum;
        float lr = reconsum * (1.f / (float)(BB * SS));
        out[131072] = lr + lk;   // loss_total
        out[131073] = lr;        // loss_recon
        out[131074] = lk;        // loss_kld
    }
}

// ---------------- launch ----------------
extern "C" void kernel_launch(void* const* d_in, const int* in_sizes, int n_in,
                              void* d_out, int out_size)
{
    (void)in_sizes; (void)n_in; (void)out_size;
    const float* X        = (const float*)d_in[0];
    const float* M        = (const float*)d_in[1];
    const float* cov      = (const float*)d_in[2];
    const float* path_h   = (const float*)d_in[3];
    const float* path_hpos= (const float*)d_in[4];
    const float* noise    = (const float*)d_in[5];
    const float* drift_w1 = (const float*)d_in[6];
    const float* drift_b1 = (const float*)d_in[7];
    const float* drift_w2 = (const float*)d_in[8];
    const float* drift_b2 = (const float*)d_in[9];
    const float* diff_w1  = (const float*)d_in[10];
    const float* diff_b1  = (const float*)d_in[11];
    const float* diff_w2  = (const float*)d_in[12];
    const float* diff_b2  = (const float*)d_in[13];
    const float* p_w1     = (const float*)d_in[14];
    const float* p_b1     = (const float*)d_in[15];
    const float* p_w2     = (const float*)d_in[16];
    const float* p_b2     = (const float*)d_in[17];
    const float* cov_w1   = (const float*)d_in[18];
    const float* cov_b1   = (const float*)d_in[19];
    const float* cov_w2   = (const float*)d_in[20];
    const float* cov_b2   = (const float*)d_in[21];
    float* out = (float*)d_out;

    float *hprior, *hpost, *ppart, *dtmp, *diffp, *states, *zw, *post, *A3, *kldp, *reconp, *Mtp;
    cudaGetSymbolAddress((void**)&hprior, g_hprior);
    cudaGetSymbolAddress((void**)&hpost,  g_hpost);
    cudaGetSymbolAddress((void**)&ppart,  g_ppart);
    cudaGetSymbolAddress((void**)&dtmp,   g_dtmp);
    cudaGetSymbolAddress((void**)&diffp,  g_diff);
    cudaGetSymbolAddress((void**)&states, g_states);
    cudaGetSymbolAddress((void**)&zw,     g_zw);
    cudaGetSymbolAddress((void**)&post,   g_post);
    cudaGetSymbolAddress((void**)&A3,     g_A3);
    cudaGetSymbolAddress((void**)&kldp,   g_kld_part);
    cudaGetSymbolAddress((void**)&reconp, g_recon_part);
    cudaGetSymbolAddress((void**)&Mtp,    g_Mt);

    static int smem_set = 0;
    if (!smem_set) {
        cudaFuncSetAttribute(scan_kernel,
                             cudaFuncAttributeMaxDynamicSharedMemorySize, SMEM_SCAN);
        smem_set = 1;
    }

    // ---- precompute (parallel over T) ----
    reset_kernel<<<1, 1>>>();
    gemm_t<PRO_PLAIN, EPI_STORE><<<dim3(16, 200), 256>>>(
        path_h, RR, drift_w1, HH, hprior, HH, RR, drift_b1,
        nullptr, nullptr, nullptr, nullptr);
    gemm_t<PRO_PLAIN, EPI_STORE><<<dim3(16, 200), 256>>>(
        path_hpos, RR, drift_w1, HH, hpost, HH, RR, drift_b1,
        nullptr, nullptr, nullptr, nullptr);
    gemm_t<PRO_PLAIN, EPI_STORE><<<dim3(16, 200), 256>>>(
        path_h, RR, p_w1, HH, ppart, HH, RR, p_b1,
        nullptr, nullptr, nullptr, nullptr);
    gemm_t<PRO_PLAIN, EPI_RELU><<<dim3(16, 200), 256>>>(
        path_h, RR, diff_w1, HH, dtmp, HH, RR, diff_b1,
        nullptr, nullptr, nullptr, nullptr);
    gemm_t<PRO_PLAIN, EPI_EXP><<<dim3(4, 200), 256>>>(
        dtmp, HH, diff_w2, ZZ, diffp, ZZ, HH, diff_b2,
        nullptr, nullptr, nullptr, nullptr);
    mt_kernel<<<(TT * BB + 255) / 256, 256>>>(M);
    z0_kernel<<<BB, 256>>>(cov, cov_w1, cov_b1, cov_w2, cov_b2);

    // ---- sequential scan: ONE persistent kernel for all 200 steps ----
    scan_kernel<<<SCAN_BLOCKS, SCAN_THREADS, SMEM_SCAN>>>(
        drift_w1 + (size_t)RR * HH, drift_w2, drift_b2, noise);

    // ---- batch epilogue (parallel over all T) ----
    gemm_t<PRO_ADDRELU, EPI_KLD><<<dim3(4, 1600), 256>>>(
        zw, HH, drift_w2, ZZ, nullptr, 0, HH, drift_b2,
        hprior, post, diffp, kldp);
    gemm_t<PRO_PLAIN, EPI_BCASTRELU><<<dim3(16, 1600), 256>>>(
        states + (size_t)BSZ * ZZ, ZZ, p_w1 + (size_t)RR * HH, HH,
        A3, HH, ZZ, nullptr, ppart, nullptr, nullptr, nullptr);
    gemm_t<PRO_PLAIN, EPI_RECON><<<dim3(2, 1600), 256>>>(
        A3, HH, p_w2, DD, nullptr, 0, HH, p_b2,
        X, Mtp, nullptr, reconp);

    // ---- output: z_final then (total, recon, kld) ----
    out_copy_kernel<<<512, 256>>>(out);
    scal_kernel<<<1, 256>>>(out);
}

// round 7
// speedup vs baseline: 3.7923x; 1.1150x over previous
#include <cuda_runtime.h>
#include <math.h>
#include <stdint.h>

#define TT 200
#define BB 64
#define SS 8
#define DD 128
#define RR 512
#define ZZ 256
#define HH 1024
#define BSZ (BB*SS)            /* 512 rows per step */
#define DT_C 0.05f
#define SQRT_DT_C 0.223606797749979f
#define LOG2PI_C 1.8378770664093453f

#define KLD_PARTS  (800*4)
#define RECON_PARTS (800*2)

#define SCAN_BLOCKS 128
#define SCAN_THREADS 128

// ---------------- device scratch (static, allocation-free) ----------------
__device__ float g_hprior[TT*BB*HH];        // h@drift_w1[:R] + b1
__device__ float g_hpost [TT*BB*HH];        // hpos@drift_w1[:R] + b1
__device__ float g_ppart [TT*BB*HH];        // h@p_w1[:R] + p_b1
__device__ float g_dtmp  [TT*BB*HH];        // relu(h@diff_w1+b1)
__device__ float g_diff  [TT*BB*ZZ];        // exp(diff MLP)
__device__ float g_Mt    [TT*BB];
__device__ float g_states[(TT+1)*BSZ*ZZ];   // z trajectory (normalized)
__device__ float g_zw    [TT*BSZ*HH];       // z_t @ drift_w1[R:]
__device__ float g_post  [TT*BSZ*ZZ];       // posterior drift
__device__ float g_A3    [TT*BSZ*HH];       // decoder hidden
__device__ float g_part  [4*BSZ*ZZ];        // split-K partials for scan
__device__ float g_kld_part[KLD_PARTS];
__device__ float g_recon_part[RECON_PARTS];
__device__ unsigned g_barcnt;

// ---------------- tf32 helpers ----------------
__device__ __forceinline__ uint32_t f2tf(float f)
{
    uint32_t u;
    asm("cvt.rna.tf32.f32 %0, %1;" : "=r"(u) : "f"(f));
    return u;
}

__device__ __forceinline__ void mma8(float* c,
    uint32_t a0, uint32_t a1, uint32_t a2, uint32_t a3,
    uint32_t b0, uint32_t b1)
{
    asm("mma.sync.aligned.m16n8k8.row.col.f32.tf32.tf32.f32 "
        "{%0,%1,%2,%3},{%4,%5,%6,%7},{%8,%9},{%0,%1,%2,%3};"
        : "+f"(c[0]), "+f"(c[1]), "+f"(c[2]), "+f"(c[3])
        : "r"(a0), "r"(a1), "r"(a2), "r"(a3), "r"(b0), "r"(b1));
}

// ---------------- generic 128x64 tf32 GEMM with fused pro/epilogues ------
// 256 threads, 8 warps in 4x2 grid, warp tile 32x32, k32 smem stages.
#define PRO_PLAIN 0
#define PRO_ADDRELU 1      // A := relu(A + aux[(m>>3)*H + k])
#define EPI_STORE 0        // C = acc (+bias)
#define EPI_RELU  1
#define EPI_EXP   2
#define EPI_BCASTRELU 3    // C = relu(acc + aux[(m>>3)*H + n])
#define EPI_KLD   4        // reduce ((0.1 tanh(acc+b)-post)/diff)^2
#define EPI_RECON 5        // reduce 0.5(log2pi+(X-(acc+b))^2)*Mt

template<int PRO, int EPI>
__global__ void __launch_bounds__(256) gemm_t(
    const float* __restrict__ A, int lda,
    const float* __restrict__ Bm, int ldb,
    float* __restrict__ C, int ldc, int K,
    const float* __restrict__ bias,
    const float* __restrict__ aux,
    const float* __restrict__ aux2,
    const float* __restrict__ aux3,
    float* __restrict__ part)
{
    __shared__ uint32_t As[128][36];   // 36%32=4 -> conflict-free frag loads
    __shared__ uint32_t Bs[32][72];    // 72%32=8 -> conflict-free frag loads
    const int tid = threadIdx.x;
    const int m0 = blockIdx.y * 128, n0 = blockIdx.x * 64;
    const int wid = tid >> 5, lane = tid & 31;
    const int wm = (wid & 3) * 32;     // warp row offset (4 warps along m)
    const int wn = (wid >> 2) * 32;    // warp col offset (2 warps along n)
    const int qr = lane >> 2;          // 0..7
    const int qc = lane & 3;           // 0..3
    const int arow = tid >> 1;         // 0..127
    const int ab   = (tid & 1) * 16;   // A stage k-base (loads 16 k)
    const int brow = tid >> 3;         // 0..31
    const int bn   = (tid & 7) * 8;    // B stage n-base (loads 8 n)

    float acc[2][4][4];
#pragma unroll
    for (int h = 0; h < 2; h++)
#pragma unroll
        for (int j = 0; j < 4; j++)
#pragma unroll
            for (int c = 0; c < 4; c++) acc[h][j][c] = 0.f;

    for (int k0 = 0; k0 < K; k0 += 32) {
#pragma unroll
        for (int i = 0; i < 4; i++) {
            float4 av = *(const float4*)&A[(size_t)(m0 + arow) * lda + k0 + ab + 4*i];
            if (PRO == PRO_ADDRELU) {
                const float4 hv = *(const float4*)&aux[(size_t)((m0 + arow) >> 3) * HH + k0 + ab + 4*i];
                av.x = fmaxf(av.x + hv.x, 0.f); av.y = fmaxf(av.y + hv.y, 0.f);
                av.z = fmaxf(av.z + hv.z, 0.f); av.w = fmaxf(av.w + hv.w, 0.f);
            }
            uint4 t;
            t.x = f2tf(av.x); t.y = f2tf(av.y); t.z = f2tf(av.z); t.w = f2tf(av.w);
            *(uint4*)&As[arow][ab + 4*i] = t;
        }
#pragma unroll
        for (int i = 0; i < 2; i++) {
            float4 bv = *(const float4*)&Bm[(size_t)(k0 + brow) * ldb + n0 + bn + 4*i];
            uint4 t;
            t.x = f2tf(bv.x); t.y = f2tf(bv.y); t.z = f2tf(bv.z); t.w = f2tf(bv.w);
            *(uint4*)&Bs[brow][bn + 4*i] = t;
        }
        __syncthreads();
#pragma unroll
        for (int k8 = 0; k8 < 4; k8++) {
            const int kk = k8 * 8;
            uint32_t a00 = As[wm + qr     ][kk + qc];
            uint32_t a01 = As[wm + qr + 8 ][kk + qc];
            uint32_t a02 = As[wm + qr     ][kk + qc + 4];
            uint32_t a03 = As[wm + qr + 8 ][kk + qc + 4];
            uint32_t a10 = As[wm + qr + 16][kk + qc];
            uint32_t a11 = As[wm + qr + 24][kk + qc];
            uint32_t a12 = As[wm + qr + 16][kk + qc + 4];
            uint32_t a13 = As[wm + qr + 24][kk + qc + 4];
#pragma unroll
            for (int j = 0; j < 4; j++) {
                const int cn = wn + j * 8 + qr;
                uint32_t b0 = Bs[kk + qc][cn];
                uint32_t b1 = Bs[kk + qc + 4][cn];
                mma8(acc[0][j], a00, a01, a02, a03, b0, b1);
                mma8(acc[1][j], a10, a11, a12, a13, b0, b1);
            }
        }
        __syncthreads();
    }

    const int mA = m0 + wm + qr;
    const int nB0 = n0 + wn + qc * 2;

    if (EPI <= 3) {
        const bool hasb = (bias != nullptr);
#pragma unroll
        for (int h = 0; h < 2; h++) {
#pragma unroll
            for (int j = 0; j < 4; j++) {
                const int n = nB0 + j * 8;
                const int r0 = mA + h * 16, r1 = r0 + 8;
                float v[4] = {acc[h][j][0], acc[h][j][1], acc[h][j][2], acc[h][j][3]};
                const int mm[4] = {r0, r0, r1, r1};
                const int nn[4] = {n, n + 1, n, n + 1};
#pragma unroll
                for (int c = 0; c < 4; c++) {
                    if (hasb) v[c] += bias[nn[c]];
                    if (EPI == EPI_RELU) v[c] = fmaxf(v[c], 0.f);
                    if (EPI == EPI_EXP)  v[c] = expf(v[c]);
                    if (EPI == EPI_BCASTRELU)
                        v[c] = fmaxf(v[c] + aux[(size_t)(mm[c] >> 3) * HH + nn[c]], 0.f);
                }
                *(float2*)&C[(size_t)r0 * ldc + n] = make_float2(v[0], v[1]);
                *(float2*)&C[(size_t)r1 * ldc + n] = make_float2(v[2], v[3]);
            }
        }
    } else {
        float s = 0.f;
#pragma unroll
        for (int h = 0; h < 2; h++) {
#pragma unroll
            for (int j = 0; j < 4; j++) {
                const int n = nB0 + j * 8;
                const int r0 = mA + h * 16, r1 = r0 + 8;
                const int mm[4] = {r0, r0, r1, r1};
                const int nn[4] = {n, n + 1, n, n + 1};
#pragma unroll
                for (int c = 0; c < 4; c++) {
                    float v = acc[h][j][c] + bias[nn[c]];
                    if (EPI == EPI_KLD) {
                        float pr = 0.1f * tanhf(v);
                        float e = (pr - aux2[(size_t)mm[c] * ZZ + nn[c]]) /
                                  aux3[(size_t)(mm[c] >> 3) * ZZ + nn[c]];
                        s += e * e;
                    } else { // EPI_RECON
                        float d = aux[(size_t)(mm[c] >> 3) * DD + nn[c]] - v;
                        float nll = 0.5f * (LOG2PI_C + d * d);
                        s += nll * aux2[mm[c] >> 3];
                    }
                }
            }
        }
        __shared__ float red[256];
        red[tid] = s;
        __syncthreads();
        for (int o = 128; o > 0; o >>= 1) {
            if (tid < o) red[tid] += red[tid + o];
            __syncthreads();
        }
        if (tid == 0) part[blockIdx.y * gridDim.x + blockIdx.x] = red[0];
    }
}

// ---------------- persistent scan kernel (tf32, 4 warps, 32x32 tiles) -----
//   W1s: tf32 [256][68]  = 69632 B   (persistent 64-col slice, 68%32=4)
//   W2s: tf32 [256][68]  = 69632 B   (persistent)
//   St : tf32 stage [64][36] = 9216 B
#define SMEM_SCAN ((256*68 + 256*68 + 64*36) * 4)

__device__ __forceinline__ void gridbar(unsigned& tgt)
{
    __syncthreads();
    if (threadIdx.x == 0) {
        __threadfence();
        atomicAdd(&g_barcnt, 1u);
        tgt += SCAN_BLOCKS;
        while (*(volatile unsigned*)&g_barcnt < tgt) { }
        __threadfence();
    }
    __syncthreads();
}

__global__ void __launch_bounds__(SCAN_THREADS, 1) scan_kernel(
    const float* __restrict__ w1z,      // drift_w1 + RR*HH
    const float* __restrict__ w2,       // drift_w2
    const float* __restrict__ b2,       // drift_b2
    const float* __restrict__ noise)
{
    extern __shared__ uint32_t smu[];
    uint32_t* W1s = smu;                     // [256][68]
    uint32_t* W2s = smu + 256*68;            // [256][68]
    uint32_t* St  = smu + 2*256*68;          // [64][36]

    const int tid = threadIdx.x;
    const int bid = blockIdx.x;
    const int wid = tid >> 5, lane = tid & 31;
    const int qr = lane >> 2;   // 0..7
    const int qc = lane & 3;    // 0..3

    // phase A geometry: 8 m-tiles (64 rows) x 16 n-slices (64 cols of 1024)
    const int bmA = bid >> 4;          // 0..7
    const int bnA = bid & 15;          // 0..15
    const int wmA = (wid & 1) * 32;    // 2 warps along m
    const int wnA = (wid >> 1) * 32;   // 2 warps along n

    // phase B1 geometry: 8 m-tiles(64r) x 4 n-tiles(64c) x 4 k-chunks(256)
    const int kcB = bid & 3;
    const int moB = (bid >> 2) >> 2;   // 0..7
    const int noB = (bid >> 2) & 3;    // 0..3
    const int wrB = (wid & 1) * 32;
    const int wcB = (wid >> 1) * 32;

    // load persistent weight slices (converted to tf32 once)
    for (int i = tid; i < 256*64; i += SCAN_THREADS) {
        int k = i >> 6, c = i & 63;
        W1s[k*68 + c] = f2tf(w1z[(size_t)k*HH + bnA*64 + c]);
    }
    for (int i = tid; i < 256*64; i += SCAN_THREADS) {
        int k = i >> 6, c = i & 63;
        W2s[k*68 + c] = f2tf(w2[(size_t)(kcB*256 + k)*ZZ + noB*64 + c]);
    }
    __syncthreads();

    unsigned tgt = 0;

    for (int t = 0; t < TT; t++) {
        const float* z = g_states + (size_t)t*BSZ*ZZ;
        float* zwt = g_zw + (size_t)t*BSZ*HH;

        // ============ phase A: zw[t] = z_t @ w1z (tf32 mma) ============
        {
            float acc[2][4][4];
#pragma unroll
            for (int h = 0; h < 2; h++)
#pragma unroll
                for (int j = 0; j < 4; j++)
#pragma unroll
                    for (int c = 0; c < 4; c++) acc[h][j][c] = 0.f;

            for (int kc = 0; kc < 8; kc++) {
                // stage 64x32 z chunk as tf32
#pragma unroll
                for (int i = 0; i < 4; i++) {
                    int idx = tid + SCAN_THREADS*i;   // 0..511
                    int row = idx >> 3, q = idx & 7;
                    float4 f = *(const float4*)&z[(size_t)(bmA*64 + row)*ZZ + kc*32 + q*4];
                    uint4 u;
                    u.x = f2tf(f.x); u.y = f2tf(f.y); u.z = f2tf(f.z); u.w = f2tf(f.w);
                    *(uint4*)&St[row*36 + q*4] = u;
                }
                __syncthreads();
#pragma unroll
                for (int k8 = 0; k8 < 4; k8++) {
                    const int kk = k8*8;
                    uint32_t a00 = St[(wmA + qr     )*36 + kk + qc];
                    uint32_t a01 = St[(wmA + qr + 8 )*36 + kk + qc];
                    uint32_t a02 = St[(wmA + qr     )*36 + kk + qc + 4];
                    uint32_t a03 = St[(wmA + qr + 8 )*36 + kk + qc + 4];
                    uint32_t a10 = St[(wmA + qr + 16)*36 + kk + qc];
                    uint32_t a11 = St[(wmA + qr + 24)*36 + kk + qc];
                    uint32_t a12 = St[(wmA + qr + 16)*36 + kk + qc + 4];
                    uint32_t a13 = St[(wmA + qr + 24)*36 + kk + qc + 4];
#pragma unroll
                    for (int j = 0; j < 4; j++) {
                        const int n = wnA + j*8 + qr;
                        uint32_t b0 = W1s[(kc*32 + kk + qc    )*68 + n];
                        uint32_t b1 = W1s[(kc*32 + kk + qc + 4)*68 + n];
                        mma8(acc[0][j], a00, a01, a02, a03, b0, b1);
                        mma8(acc[1][j], a10, a11, a12, a13, b0, b1);
                    }
                }
                __syncthreads();
            }
            const int mA = bmA*64 + wmA + qr;
#pragma unroll
            for (int h = 0; h < 2; h++) {
#pragma unroll
                for (int j = 0; j < 4; j++) {
                    const int n = bnA*64 + wnA + j*8 + qc*2;
                    const int r0 = mA + h*16;
                    *(float2*)&zwt[(size_t)r0*HH + n]     = make_float2(acc[h][j][0], acc[h][j][1]);
                    *(float2*)&zwt[(size_t)(r0+8)*HH + n] = make_float2(acc[h][j][2], acc[h][j][3]);
                }
            }
        }
        gridbar(tgt);

        // ============ phase B1: partial relu(zw+hpost)@W2 (tf32 mma) ============
        {
            const float* hp = g_hpost + (size_t)t*BB*HH;
            float acc[2][4][4];
#pragma unroll
            for (int h = 0; h < 2; h++)
#pragma unroll
                for (int j = 0; j < 4; j++)
#pragma unroll
                    for (int c = 0; c < 4; c++) acc[h][j][c] = 0.f;

            for (int kc = 0; kc < 8; kc++) {
                // stage 64x32 hidden chunk (relu(zw+hpost)) as tf32
#pragma unroll
                for (int i = 0; i < 4; i++) {
                    int idx = tid + SCAN_THREADS*i;   // 0..511
                    int row = idx >> 3, q = idx & 7;
                    int gk = kcB*256 + kc*32 + q*4;
                    float4 f = *(const float4*)&zwt[(size_t)(moB*64 + row)*HH + gk];
                    float4 h4 = *(const float4*)&hp[(size_t)((moB*64 + row) >> 3)*HH + gk];
                    uint4 u;
                    u.x = f2tf(fmaxf(f.x + h4.x, 0.f));
                    u.y = f2tf(fmaxf(f.y + h4.y, 0.f));
                    u.z = f2tf(fmaxf(f.z + h4.z, 0.f));
                    u.w = f2tf(fmaxf(f.w + h4.w, 0.f));
                    *(uint4*)&St[row*36 + q*4] = u;
                }
                __syncthreads();
#pragma unroll
                for (int k8 = 0; k8 < 4; k8++) {
                    const int kk = k8*8;
                    uint32_t a00 = St[(wrB + qr     )*36 + kk + qc];
                    uint32_t a01 = St[(wrB + qr + 8 )*36 + kk + qc];
                    uint32_t a02 = St[(wrB + qr     )*36 + kk + qc + 4];
                    uint32_t a03 = St[(wrB + qr + 8 )*36 + kk + qc + 4];
                    uint32_t a10 = St[(wrB + qr + 16)*36 + kk + qc];
                    uint32_t a11 = St[(wrB + qr + 24)*36 + kk + qc];
                    uint32_t a12 = St[(wrB + qr + 16)*36 + kk + qc + 4];
                    uint32_t a13 = St[(wrB + qr + 24)*36 + kk + qc + 4];
#pragma unroll
                    for (int j = 0; j < 4; j++) {
                        const int n = wcB + j*8 + qr;
                        uint32_t b0 = W2s[(kc*32 + kk + qc    )*68 + n];
                        uint32_t b1 = W2s[(kc*32 + kk + qc + 4)*68 + n];
                        mma8(acc[0][j], a00, a01, a02, a03, b0, b1);
                        mma8(acc[1][j], a10, a11, a12, a13, b0, b1);
                    }
                }
                __syncthreads();
            }
            float* gp = g_part + (size_t)kcB*BSZ*ZZ;
            const int mB = moB*64 + wrB + qr;
#pragma unroll
            for (int h = 0; h < 2; h++) {
#pragma unroll
                for (int j = 0; j < 4; j++) {
                    const int n = noB*64 + wcB + j*8 + qc*2;
                    const int r0 = mB + h*16;
                    *(float2*)&gp[(size_t)r0*ZZ + n]     = make_float2(acc[h][j][0], acc[h][j][1]);
                    *(float2*)&gp[(size_t)(r0+8)*ZZ + n] = make_float2(acc[h][j][2], acc[h][j][3]);
                }
            }
        }
        gridbar(tgt);

        // ============ phase B2: combine + tanh + Euler + row minmax (fp32) ============
        {
            const int row = bid*4 + wid;
            const float* zr = g_states + (size_t)t*BSZ*ZZ + (size_t)row*ZZ;
            const float* nr = noise + (size_t)t*BSZ*ZZ + (size_t)row*ZZ;
            const float* dr = g_diff + ((size_t)t*BB + (row >> 3))*ZZ;
            float* pr = g_post + (size_t)t*BSZ*ZZ + (size_t)row*ZZ;
            float* outz = g_states + (size_t)(t+1)*BSZ*ZZ + (size_t)row*ZZ;

            float v8[8];
            float vmin = 3.4e38f, vmax = -3.4e38f;
#pragma unroll
            for (int j = 0; j < 2; j++) {
                const int cb = lane*4 + 128*j;
                float4 s  = *(const float4*)&g_part[0*BSZ*ZZ + (size_t)row*ZZ + cb];
                float4 s1 = *(const float4*)&g_part[1*BSZ*ZZ + (size_t)row*ZZ + cb];
                float4 s2 = *(const float4*)&g_part[2*BSZ*ZZ + (size_t)row*ZZ + cb];
                float4 s3 = *(const float4*)&g_part[3*BSZ*ZZ + (size_t)row*ZZ + cb];
                float4 bb = *(const float4*)&b2[cb];
                float4 zv = *(const float4*)&zr[cb];
                float4 nv = *(const float4*)&nr[cb];
                float4 dv = *(const float4*)&dr[cb];
                float pd0 = 0.1f * tanhf(s.x + s1.x + s2.x + s3.x + bb.x);
                float pd1 = 0.1f * tanhf(s.y + s1.y + s2.y + s3.y + bb.y);
                float pd2 = 0.1f * tanhf(s.z + s1.z + s2.z + s3.z + bb.z);
                float pd3 = 0.1f * tanhf(s.w + s1.w + s2.w + s3.w + bb.w);
                *(float4*)&pr[cb] = make_float4(pd0, pd1, pd2, pd3);
                float n0v = zv.x + DT_C*pd0 + SQRT_DT_C*dv.x*nv.x;
                float n1v = zv.y + DT_C*pd1 + SQRT_DT_C*dv.y*nv.y;
                float n2v = zv.z + DT_C*pd2 + SQRT_DT_C*dv.z*nv.z;
                float n3v = zv.w + DT_C*pd3 + SQRT_DT_C*dv.w*nv.w;
                v8[j*4+0] = n0v; v8[j*4+1] = n1v; v8[j*4+2] = n2v; v8[j*4+3] = n3v;
                vmin = fminf(vmin, fminf(fminf(n0v, n1v), fminf(n2v, n3v)));
                vmax = fmaxf(vmax, fmaxf(fmaxf(n0v, n1v), fmaxf(n2v, n3v)));
            }
#pragma unroll
            for (int o = 16; o > 0; o >>= 1) {
                vmin = fminf(vmin, __shfl_xor_sync(0xffffffffu, vmin, o));
                vmax = fmaxf(vmax, __shfl_xor_sync(0xffffffffu, vmax, o));
            }
            const float inv = 1.f / (vmax - vmin);
#pragma unroll
            for (int j = 0; j < 2; j++) {
                const int cb = lane*4 + 128*j;
                *(float4*)&outz[cb] = make_float4((v8[j*4+0]-vmin)*inv, (v8[j*4+1]-vmin)*inv,
                                                  (v8[j*4+2]-vmin)*inv, (v8[j*4+3]-vmin)*inv);
            }
        }
        gridbar(tgt);
    }
}

// ---------------- small kernels ----------------
__global__ void reset_kernel() { g_barcnt = 0u; }

__global__ void mt_kernel(const float* __restrict__ M)
{
    int r = blockIdx.x * blockDim.x + threadIdx.x;
    if (r < TT * BB) {
        const float* p = M + (size_t)r * DD;
        float s = 0.f;
        for (int d = 0; d < DD; d++) s += p[d];
        g_Mt[r] = s * (1.f / DD);
    }
}

__global__ void z0_kernel(const float* __restrict__ cov,
                          const float* __restrict__ w1, const float* __restrict__ b1,
                          const float* __restrict__ w2, const float* __restrict__ b2)
{
    int b = blockIdx.x;
    __shared__ float cv[16];
    __shared__ float hid[64];
    if (threadIdx.x < 16) cv[threadIdx.x] = cov[b * 16 + threadIdx.x];
    __syncthreads();
    if (threadIdx.x < 64) {
        float s = b1[threadIdx.x];
        for (int i = 0; i < 16; i++) s += cv[i] * w1[i * 64 + threadIdx.x];
        hid[threadIdx.x] = fmaxf(s, 0.f);
    }
    __syncthreads();
    int n = threadIdx.x;
    float s = b2[n];
    for (int j = 0; j < 64; j++) s += hid[j] * w2[j * 256 + n];
    float z = tanhf(s);
    for (int ss = 0; ss < SS; ss++)
        g_states[(size_t)(b * SS + ss) * ZZ + n] = z;
}

__global__ void out_copy_kernel(float* __restrict__ out)
{
    int i = blockIdx.x * 256 + threadIdx.x;
    out[i] = g_states[(size_t)TT * BSZ * ZZ + i];
}

__global__ void scal_kernel(float* __restrict__ out)
{
    __shared__ float red[256];
    int tid = threadIdx.x;
    float s = 0.f;
    for (int i = tid; i < KLD_PARTS; i += 256) s += g_kld_part[i];
    red[tid] = s;
    __syncthreads();
    for (int o = 128; o > 0; o >>= 1) { if (tid < o) red[tid] += red[tid + o]; __syncthreads(); }
    float kldsum = red[0];
    __syncthreads();
    s = 0.f;
    for (int i = tid; i < RECON_PARTS; i += 256) s += g_recon_part[i];
    red[tid] = s;
    __syncthreads();
    for (int o = 128; o > 0; o >>= 1) { if (tid < o) red[tid] += red[tid + o]; __syncthreads(); }
    if (tid == 0) {
        float reconsum = red[0];
        float lk = (0.5f * DT_C / (float)(BB * SS)) * kldsum;
        float lr = reconsum * (1.f / (float)(BB * SS));
        out[131072] = lr + lk;   // loss_total
        out[131073] = lr;        // loss_recon
        out[131074] = lk;        // loss_kld
    }
}

// ---------------- launch ----------------
extern "C" void kernel_launch(void* const* d_in, const int* in_sizes, int n_in,
                              void* d_out, int out_size)
{
    (void)in_sizes; (void)n_in; (void)out_size;
    const float* X        = (const float*)d_in[0];
    const float* M        = (const float*)d_in[1];
    const float* cov      = (const float*)d_in[2];
    const float* path_h   = (const float*)d_in[3];
    const float* path_hpos= (const float*)d_in[4];
    const float* noise    = (const float*)d_in[5];
    const float* drift_w1 = (const float*)d_in[6];
    const float* drift_b1 = (const float*)d_in[7];
    const float* drift_w2 = (const float*)d_in[8];
    const float* drift_b2 = (const float*)d_in[9];
    const float* diff_w1  = (const float*)d_in[10];
    const float* diff_b1  = (const float*)d_in[11];
    const float* diff_w2  = (const float*)d_in[12];
    const float* diff_b2  = (const float*)d_in[13];
    const float* p_w1     = (const float*)d_in[14];
    const float* p_b1     = (const float*)d_in[15];
    const float* p_w2     = (const float*)d_in[16];
    const float* p_b2     = (const float*)d_in[17];
    const float* cov_w1   = (const float*)d_in[18];
    const float* cov_b1   = (const float*)d_in[19];
    const float* cov_w2   = (const float*)d_in[20];
    const float* cov_b2   = (const float*)d_in[21];
    float* out = (float*)d_out;

    float *hprior, *hpost, *ppart, *dtmp, *diffp, *states, *zw, *post, *A3, *kldp, *reconp, *Mtp;
    cudaGetSymbolAddress((void**)&hprior, g_hprior);
    cudaGetSymbolAddress((void**)&hpost,  g_hpost);
    cudaGetSymbolAddress((void**)&ppart,  g_ppart);
    cudaGetSymbolAddress((void**)&dtmp,   g_dtmp);
    cudaGetSymbolAddress((void**)&diffp,  g_diff);
    cudaGetSymbolAddress((void**)&states, g_states);
    cudaGetSymbolAddress((void**)&zw,     g_zw);
    cudaGetSymbolAddress((void**)&post,   g_post);
    cudaGetSymbolAddress((void**)&A3,     g_A3);
    cudaGetSymbolAddress((void**)&kldp,   g_kld_part);
    cudaGetSymbolAddress((void**)&reconp, g_recon_part);
    cudaGetSymbolAddress((void**)&Mtp,    g_Mt);

    static int smem_set = 0;
    if (!smem_set) {
        cudaFuncSetAttribute(scan_kernel,
                             cudaFuncAttributeMaxDynamicSharedMemorySize, SMEM_SCAN);
        smem_set = 1;
    }

    // ---- precompute (parallel over T) ----
    reset_kernel<<<1, 1>>>();
    gemm_t<PRO_PLAIN, EPI_STORE><<<dim3(16, 100), 256>>>(
        path_h, RR, drift_w1, HH, hprior, HH, RR, drift_b1,
        nullptr, nullptr, nullptr, nullptr);
    gemm_t<PRO_PLAIN, EPI_STORE><<<dim3(16, 100), 256>>>(
        path_hpos, RR, drift_w1, HH, hpost, HH, RR, drift_b1,
        nullptr, nullptr, nullptr, nullptr);
    gemm_t<PRO_PLAIN, EPI_STORE><<<dim3(16, 100), 256>>>(
        path_h, RR, p_w1, HH, ppart, HH, RR, p_b1,
        nullptr, nullptr, nullptr, nullptr);
    gemm_t<PRO_PLAIN, EPI_RELU><<<dim3(16, 100), 256>>>(
        path_h, RR, diff_w1, HH, dtmp, HH, RR, diff_b1,
        nullptr, nullptr, nullptr, nullptr);
    gemm_t<PRO_PLAIN, EPI_EXP><<<dim3(4, 100), 256>>>(
        dtmp, HH, diff_w2, ZZ, diffp, ZZ, HH, diff_b2,
        nullptr, nullptr, nullptr, nullptr);
    mt_kernel<<<(TT * BB + 255) / 256, 256>>>(M);
    z0_kernel<<<BB, 256>>>(cov, cov_w1, cov_b1, cov_w2, cov_b2);

    // ---- sequential scan: ONE persistent kernel for all 200 steps ----
    scan_kernel<<<SCAN_BLOCKS, SCAN_THREADS, SMEM_SCAN>>>(
        drift_w1 + (size_t)RR * HH, drift_w2, drift_b2, noise);

    // ---- batch epilogue (parallel over all T) ----
    gemm_t<PRO_ADDRELU, EPI_KLD><<<dim3(4, 800), 256>>>(
        zw, HH, drift_w2, ZZ, nullptr, 0, HH, drift_b2,
        hprior, post, diffp, kldp);
    gemm_t<PRO_PLAIN, EPI_BCASTRELU><<<dim3(16, 800), 256>>>(
        states + (size_t)BSZ * ZZ, ZZ, p_w1 + (size_t)RR * HH, HH,
        A3, HH, ZZ, nullptr, ppart, nullptr, nullptr, nullptr);
    gemm_t<PRO_PLAIN, EPI_RECON><<<dim3(2, 800), 256>>>(
        A3, HH, p_w2, DD, nullptr, 0, HH, p_b2,
        X, Mtp, nullptr, reconp);

    // ---- output: z_final then (total, recon, kld) ----
    out_copy_kernel<<<512, 256>>>(out);
    scal_kernel<<<1, 256>>>(out);
}

// round 8
// speedup vs baseline: 3.9841x; 1.0506x over previous
#include <cuda_runtime.h>
#include <math.h>
#include <stdint.h>

#define TT 200
#define BB 64
#define SS 8
#define DD 128
#define RR 512
#define ZZ 256
#define HH 1024
#define BSZ (BB*SS)            /* 512 rows per step */
#define DT_C 0.05f
#define SQRT_DT_C 0.223606797749979f
#define LOG2PI_C 1.8378770664093453f

#define KLD_PARTS  (800*4)
#define RECON_PARTS (800*2)

#define SCAN_BLOCKS 128
#define SCAN_THREADS 128

// ---------------- device scratch (static, allocation-free) ----------------
__device__ float g_hprior[TT*BB*HH];        // h@drift_w1[:R] + b1
__device__ float g_hpost [TT*BB*HH];        // hpos@drift_w1[:R] + b1
__device__ float g_ppart [TT*BB*HH];        // h@p_w1[:R] + p_b1
__device__ float g_dtmp  [TT*BB*HH];        // relu(h@diff_w1+b1)
__device__ float g_diff  [TT*BB*ZZ];        // exp(diff MLP)
__device__ float g_Mt    [TT*BB];
__device__ float g_states[(TT+1)*BSZ*ZZ];   // z trajectory (normalized)
__device__ float g_zw    [TT*BSZ*HH];       // z_t @ drift_w1[R:]
__device__ float g_post  [TT*BSZ*ZZ];       // posterior drift
__device__ float g_A3    [TT*BSZ*HH];       // decoder hidden
__device__ float g_part  [4*BSZ*ZZ];        // split-K partials for scan
__device__ float g_kld_part[KLD_PARTS];
__device__ float g_recon_part[RECON_PARTS];
__device__ unsigned g_cnt[32*32];           // spread barrier counters (128B apart)

// ---------------- tf32 helpers ----------------
__device__ __forceinline__ uint32_t f2tf(float f)
{
    uint32_t u;
    asm("cvt.rna.tf32.f32 %0, %1;" : "=r"(u) : "f"(f));
    return u;
}

__device__ __forceinline__ void mma8(float* c,
    uint32_t a0, uint32_t a1, uint32_t a2, uint32_t a3,
    uint32_t b0, uint32_t b1)
{
    asm("mma.sync.aligned.m16n8k8.row.col.f32.tf32.tf32.f32 "
        "{%0,%1,%2,%3},{%4,%5,%6,%7},{%8,%9},{%0,%1,%2,%3};"
        : "+f"(c[0]), "+f"(c[1]), "+f"(c[2]), "+f"(c[3])
        : "r"(a0), "r"(a1), "r"(a2), "r"(a3), "r"(b0), "r"(b1));
}

// ---------------- generic 128x64 tf32 GEMM with fused pro/epilogues ------
// 256 threads, 8 warps in 4x2 grid, warp tile 32x32, k32 smem stages.
#define PRO_PLAIN 0
#define PRO_ADDRELU 1      // A := relu(A + aux[(m>>3)*H + k])
#define EPI_STORE 0        // C = acc (+bias)
#define EPI_RELU  1
#define EPI_EXP   2
#define EPI_BCASTRELU 3    // C = relu(acc + aux[(m>>3)*H + n])
#define EPI_KLD   4        // reduce ((0.1 tanh(acc+b)-post)/diff)^2
#define EPI_RECON 5        // reduce 0.5(log2pi+(X-(acc+b))^2)*Mt

template<int PRO, int EPI>
__global__ void __launch_bounds__(256) gemm_t(
    const float* __restrict__ A, int lda,
    const float* __restrict__ Bm, int ldb,
    float* __restrict__ C, int ldc, int K,
    const float* __restrict__ bias,
    const float* __restrict__ aux,
    const float* __restrict__ aux2,
    const float* __restrict__ aux3,
    float* __restrict__ part)
{
    __shared__ uint32_t As[128][36];   // 36%32=4 -> conflict-free frag loads
    __shared__ uint32_t Bs[32][72];    // 72%32=8 -> conflict-free frag loads
    const int tid = threadIdx.x;
    const int m0 = blockIdx.y * 128, n0 = blockIdx.x * 64;
    const int wid = tid >> 5, lane = tid & 31;
    const int wm = (wid & 3) * 32;     // warp row offset (4 warps along m)
    const int wn = (wid >> 2) * 32;    // warp col offset (2 warps along n)
    const int qr = lane >> 2;          // 0..7
    const int qc = lane & 3;           // 0..3
    const int arow = tid >> 1;         // 0..127
    const int ab   = (tid & 1) * 16;   // A stage k-base (loads 16 k)
    const int brow = tid >> 3;         // 0..31
    const int bn   = (tid & 7) * 8;    // B stage n-base (loads 8 n)

    float acc[2][4][4];
#pragma unroll
    for (int h = 0; h < 2; h++)
#pragma unroll
        for (int j = 0; j < 4; j++)
#pragma unroll
            for (int c = 0; c < 4; c++) acc[h][j][c] = 0.f;

    for (int k0 = 0; k0 < K; k0 += 32) {
#pragma unroll
        for (int i = 0; i < 4; i++) {
            float4 av = *(const float4*)&A[(size_t)(m0 + arow) * lda + k0 + ab + 4*i];
            if (PRO == PRO_ADDRELU) {
                const float4 hv = *(const float4*)&aux[(size_t)((m0 + arow) >> 3) * HH + k0 + ab + 4*i];
                av.x = fmaxf(av.x + hv.x, 0.f); av.y = fmaxf(av.y + hv.y, 0.f);
                av.z = fmaxf(av.z + hv.z, 0.f); av.w = fmaxf(av.w + hv.w, 0.f);
            }
            uint4 t;
            t.x = f2tf(av.x); t.y = f2tf(av.y); t.z = f2tf(av.z); t.w = f2tf(av.w);
            *(uint4*)&As[arow][ab + 4*i] = t;
        }
#pragma unroll
        for (int i = 0; i < 2; i++) {
            float4 bv = *(const float4*)&Bm[(size_t)(k0 + brow) * ldb + n0 + bn + 4*i];
            uint4 t;
            t.x = f2tf(bv.x); t.y = f2tf(bv.y); t.z = f2tf(bv.z); t.w = f2tf(bv.w);
            *(uint4*)&Bs[brow][bn + 4*i] = t;
        }
        __syncthreads();
#pragma unroll
        for (int k8 = 0; k8 < 4; k8++) {
            const int kk = k8 * 8;
            uint32_t a00 = As[wm + qr     ][kk + qc];
            uint32_t a01 = As[wm + qr + 8 ][kk + qc];
            uint32_t a02 = As[wm + qr     ][kk + qc + 4];
            uint32_t a03 = As[wm + qr + 8 ][kk + qc + 4];
            uint32_t a10 = As[wm + qr + 16][kk + qc];
            uint32_t a11 = As[wm + qr + 24][kk + qc];
            uint32_t a12 = As[wm + qr + 16][kk + qc + 4];
            uint32_t a13 = As[wm + qr + 24][kk + qc + 4];
#pragma unroll
            for (int j = 0; j < 4; j++) {
                const int cn = wn + j * 8 + qr;
                uint32_t b0 = Bs[kk + qc][cn];
                uint32_t b1 = Bs[kk + qc + 4][cn];
                mma8(acc[0][j], a00, a01, a02, a03, b0, b1);
                mma8(acc[1][j], a10, a11, a12, a13, b0, b1);
            }
        }
        __syncthreads();
    }

    const int mA = m0 + wm + qr;
    const int nB0 = n0 + wn + qc * 2;

    if (EPI <= 3) {
        const bool hasb = (bias != nullptr);
#pragma unroll
        for (int h = 0; h < 2; h++) {
#pragma unroll
            for (int j = 0; j < 4; j++) {
                const int n = nB0 + j * 8;
                const int r0 = mA + h * 16, r1 = r0 + 8;
                float v[4] = {acc[h][j][0], acc[h][j][1], acc[h][j][2], acc[h][j][3]};
                const int mm[4] = {r0, r0, r1, r1};
                const int nn[4] = {n, n + 1, n, n + 1};
#pragma unroll
                for (int c = 0; c < 4; c++) {
                    if (hasb) v[c] += bias[nn[c]];
                    if (EPI == EPI_RELU) v[c] = fmaxf(v[c], 0.f);
                    if (EPI == EPI_EXP)  v[c] = expf(v[c]);
                    if (EPI == EPI_BCASTRELU)
                        v[c] = fmaxf(v[c] + aux[(size_t)(mm[c] >> 3) * HH + nn[c]], 0.f);
                }
                *(float2*)&C[(size_t)r0 * ldc + n] = make_float2(v[0], v[1]);
                *(float2*)&C[(size_t)r1 * ldc + n] = make_float2(v[2], v[3]);
            }
        }
    } else {
        float s = 0.f;
#pragma unroll
        for (int h = 0; h < 2; h++) {
#pragma unroll
            for (int j = 0; j < 4; j++) {
                const int n = nB0 + j * 8;
                const int r0 = mA + h * 16, r1 = r0 + 8;
                const int mm[4] = {r0, r0, r1, r1};
                const int nn[4] = {n, n + 1, n, n + 1};
#pragma unroll
                for (int c = 0; c < 4; c++) {
                    float v = acc[h][j][c] + bias[nn[c]];
                    if (EPI == EPI_KLD) {
                        float pr = 0.1f * tanhf(v);
                        float e = (pr - aux2[(size_t)mm[c] * ZZ + nn[c]]) /
                                  aux3[(size_t)(mm[c] >> 3) * ZZ + nn[c]];
                        s += e * e;
                    } else { // EPI_RECON
                        float d = aux[(size_t)(mm[c] >> 3) * DD + nn[c]] - v;
                        float nll = 0.5f * (LOG2PI_C + d * d);
                        s += nll * aux2[mm[c] >> 3];
                    }
                }
            }
        }
        __shared__ float red[256];
        red[tid] = s;
        __syncthreads();
        for (int o = 128; o > 0; o >>= 1) {
            if (tid < o) red[tid] += red[tid + o];
            __syncthreads();
        }
        if (tid == 0) part[blockIdx.y * gridDim.x + blockIdx.x] = red[0];
    }
}

// ---------------- persistent scan kernel (tf32, 4 warps, 32x32 tiles) -----
//   W1s: tf32 [256][72]  = 73728 B   (persistent, 72%32=8 conflict-free)
//   W2s: tf32 [256][72]  = 73728 B   (persistent)
//   St : tf32 stage [64][260] = 66560 B (full 64x256 tile, 260%32=4)
#define SMEM_SCAN ((256*72*2 + 64*260) * 4)

__device__ __forceinline__ void gridbar(unsigned& tgt)
{
    tgt += SCAN_BLOCKS;
    __syncthreads();
    if (threadIdx.x == 0) {
        __threadfence();
        atomicAdd(&g_cnt[(blockIdx.x & 31) << 5], 1u);
    }
    if (threadIdx.x < 32) {
        unsigned s;
        do {
            s = *(volatile unsigned*)&g_cnt[threadIdx.x << 5];
#pragma unroll
            for (int o = 16; o > 0; o >>= 1)
                s += __shfl_xor_sync(0xffffffffu, s, o);
        } while (s < tgt);
        __threadfence();
    }
    __syncthreads();
}

__global__ void __launch_bounds__(SCAN_THREADS, 1) scan_kernel(
    const float* __restrict__ w1z,      // drift_w1 + RR*HH
    const float* __restrict__ w2,       // drift_w2
    const float* __restrict__ b2,       // drift_b2
    const float* __restrict__ noise)
{
    extern __shared__ uint32_t smu[];
    uint32_t* W1s = smu;                     // [256][72]
    uint32_t* W2s = smu + 256*72;            // [256][72]
    uint32_t* St  = smu + 2*256*72;          // [64][260]

    const int tid = threadIdx.x;
    const int bid = blockIdx.x;
    const int wid = tid >> 5, lane = tid & 31;
    const int qr = lane >> 2;   // 0..7
    const int qc = lane & 3;    // 0..3

    // phase A geometry: 8 m-tiles (64 rows) x 16 n-slices (64 cols of 1024)
    const int bmA = bid >> 4;          // 0..7
    const int bnA = bid & 15;          // 0..15
    const int wmA = (wid & 1) * 32;    // 2 warps along m
    const int wnA = (wid >> 1) * 32;   // 2 warps along n

    // phase B1 geometry: 8 m-tiles(64r) x 4 n-tiles(64c) x 4 k-chunks(256)
    const int kcB = bid & 3;
    const int moB = (bid >> 2) >> 2;   // 0..7
    const int noB = (bid >> 2) & 3;    // 0..3
    const int wrB = (wid & 1) * 32;
    const int wcB = (wid >> 1) * 32;

    // load persistent weight slices (converted to tf32 once)
    for (int i = tid; i < 256*64; i += SCAN_THREADS) {
        int k = i >> 6, c = i & 63;
        W1s[k*72 + c] = f2tf(w1z[(size_t)k*HH + bnA*64 + c]);
        W2s[k*72 + c] = f2tf(w2[(size_t)(kcB*256 + k)*ZZ + noB*64 + c]);
    }
    __syncthreads();

    unsigned tgt = 0;

    for (int t = 0; t < TT; t++) {
        const float* z = g_states + (size_t)t*BSZ*ZZ;
        float* zwt = g_zw + (size_t)t*BSZ*HH;

        // ============ phase A: zw[t] = z_t @ w1z (tf32 mma) ============
        {
            // stage full 64x256 z tile as tf32 (one sync)
            for (int i = tid; i < 64*64; i += SCAN_THREADS) {
                int row = i >> 6, q = (i & 63) << 2;
                float4 f = *(const float4*)&z[(size_t)(bmA*64 + row)*ZZ + q];
                uint4 u;
                u.x = f2tf(f.x); u.y = f2tf(f.y); u.z = f2tf(f.z); u.w = f2tf(f.w);
                *(uint4*)&St[row*260 + q] = u;
            }
            __syncthreads();

            float acc[2][4][4];
#pragma unroll
            for (int h = 0; h < 2; h++)
#pragma unroll
                for (int j = 0; j < 4; j++)
#pragma unroll
                    for (int c = 0; c < 4; c++) acc[h][j][c] = 0.f;

#pragma unroll 4
            for (int kb = 0; kb < 32; kb++) {
                const int kk = kb * 8;
                uint32_t a00 = St[(wmA + qr     )*260 + kk + qc];
                uint32_t a01 = St[(wmA + qr + 8 )*260 + kk + qc];
                uint32_t a02 = St[(wmA + qr     )*260 + kk + qc + 4];
                uint32_t a03 = St[(wmA + qr + 8 )*260 + kk + qc + 4];
                uint32_t a10 = St[(wmA + qr + 16)*260 + kk + qc];
                uint32_t a11 = St[(wmA + qr + 24)*260 + kk + qc];
                uint32_t a12 = St[(wmA + qr + 16)*260 + kk + qc + 4];
                uint32_t a13 = St[(wmA + qr + 24)*260 + kk + qc + 4];
#pragma unroll
                for (int j = 0; j < 4; j++) {
                    const int n = wnA + j*8 + qr;
                    uint32_t b0 = W1s[(kk + qc    )*72 + n];
                    uint32_t b1 = W1s[(kk + qc + 4)*72 + n];
                    mma8(acc[0][j], a00, a01, a02, a03, b0, b1);
                    mma8(acc[1][j], a10, a11, a12, a13, b0, b1);
                }
            }
            const int mA = bmA*64 + wmA + qr;
#pragma unroll
            for (int h = 0; h < 2; h++) {
#pragma unroll
                for (int j = 0; j < 4; j++) {
                    const int n = bnA*64 + wnA + j*8 + qc*2;
                    const int r0 = mA + h*16;
                    *(float2*)&zwt[(size_t)r0*HH + n]     = make_float2(acc[h][j][0], acc[h][j][1]);
                    *(float2*)&zwt[(size_t)(r0+8)*HH + n] = make_float2(acc[h][j][2], acc[h][j][3]);
                }
            }
        }
        gridbar(tgt);

        // ============ phase B1: partial relu(zw+hpost)@W2 (tf32 mma) ============
        {
            const float* hp = g_hpost + (size_t)t*BB*HH;
            // stage full 64x256 hidden chunk relu(zw+hpost) as tf32 (one sync)
            for (int i = tid; i < 64*64; i += SCAN_THREADS) {
                int row = i >> 6, q = (i & 63) << 2;
                int gk = kcB*256 + q;
                float4 f  = *(const float4*)&zwt[(size_t)(moB*64 + row)*HH + gk];
                float4 h4 = *(const float4*)&hp[(size_t)((moB*64 + row) >> 3)*HH + gk];
                uint4 u;
                u.x = f2tf(fmaxf(f.x + h4.x, 0.f));
                u.y = f2tf(fmaxf(f.y + h4.y, 0.f));
                u.z = f2tf(fmaxf(f.z + h4.z, 0.f));
                u.w = f2tf(fmaxf(f.w + h4.w, 0.f));
                *(uint4*)&St[row*260 + q] = u;
            }
            __syncthreads();

            float acc[2][4][4];
#pragma unroll
            for (int h = 0; h < 2; h++)
#pragma unroll
                for (int j = 0; j < 4; j++)
#pragma unroll
                    for (int c = 0; c < 4; c++) acc[h][j][c] = 0.f;

#pragma unroll 4
            for (int kb = 0; kb < 32; kb++) {
                const int kk = kb * 8;
                uint32_t a00 = St[(wrB + qr     )*260 + kk + qc];
                uint32_t a01 = St[(wrB + qr + 8 )*260 + kk + qc];
                uint32_t a02 = St[(wrB + qr     )*260 + kk + qc + 4];
                uint32_t a03 = St[(wrB + qr + 8 )*260 + kk + qc + 4];
                uint32_t a10 = St[(wrB + qr + 16)*260 + kk + qc];
                uint32_t a11 = St[(wrB + qr + 24)*260 + kk + qc];
                uint32_t a12 = St[(wrB + qr + 16)*260 + kk + qc + 4];
                uint32_t a13 = St[(wrB + qr + 24)*260 + kk + qc + 4];
#pragma unroll
                for (int j = 0; j < 4; j++) {
                    const int n = wcB + j*8 + qr;
                    uint32_t b0 = W2s[(kk + qc    )*72 + n];
                    uint32_t b1 = W2s[(kk + qc + 4)*72 + n];
                    mma8(acc[0][j], a00, a01, a02, a03, b0, b1);
                    mma8(acc[1][j], a10, a11, a12, a13, b0, b1);
                }
            }
            float* gp = g_part + (size_t)kcB*BSZ*ZZ;
            const int mB = moB*64 + wrB + qr;
#pragma unroll
            for (int h = 0; h < 2; h++) {
#pragma unroll
                for (int j = 0; j < 4; j++) {
                    const int n = noB*64 + wcB + j*8 + qc*2;
                    const int r0 = mB + h*16;
                    *(float2*)&gp[(size_t)r0*ZZ + n]     = make_float2(acc[h][j][0], acc[h][j][1]);
                    *(float2*)&gp[(size_t)(r0+8)*ZZ + n] = make_float2(acc[h][j][2], acc[h][j][3]);
                }
            }
        }
        gridbar(tgt);

        // ============ phase B2: combine + tanh + Euler + row minmax (fp32) ============
        {
            const int row = bid*4 + wid;
            const float* zr = g_states + (size_t)t*BSZ*ZZ + (size_t)row*ZZ;
            const float* nr = noise + (size_t)t*BSZ*ZZ + (size_t)row*ZZ;
            const float* dr = g_diff + ((size_t)t*BB + (row >> 3))*ZZ;
            float* pr = g_post + (size_t)t*BSZ*ZZ + (size_t)row*ZZ;
            float* outz = g_states + (size_t)(t+1)*BSZ*ZZ + (size_t)row*ZZ;

            float v8[8];
            float vmin = 3.4e38f, vmax = -3.4e38f;
#pragma unroll
            for (int j = 0; j < 2; j++) {
                const int cb = lane*4 + 128*j;
                float4 s  = *(const float4*)&g_part[0*BSZ*ZZ + (size_t)row*ZZ + cb];
                float4 s1 = *(const float4*)&g_part[1*BSZ*ZZ + (size_t)row*ZZ + cb];
                float4 s2 = *(const float4*)&g_part[2*BSZ*ZZ + (size_t)row*ZZ + cb];
                float4 s3 = *(const float4*)&g_part[3*BSZ*ZZ + (size_t)row*ZZ + cb];
                float4 bb = *(const float4*)&b2[cb];
                float4 zv = *(const float4*)&zr[cb];
                float4 nv = *(const float4*)&nr[cb];
                float4 dv = *(const float4*)&dr[cb];
                float pd0 = 0.1f * tanhf(s.x + s1.x + s2.x + s3.x + bb.x);
                float pd1 = 0.1f * tanhf(s.y + s1.y + s2.y + s3.y + bb.y);
                float pd2 = 0.1f * tanhf(s.z + s1.z + s2.z + s3.z + bb.z);
                float pd3 = 0.1f * tanhf(s.w + s1.w + s2.w + s3.w + bb.w);
                *(float4*)&pr[cb] = make_float4(pd0, pd1, pd2, pd3);
                float n0v = zv.x + DT_C*pd0 + SQRT_DT_C*dv.x*nv.x;
                float n1v = zv.y + DT_C*pd1 + SQRT_DT_C*dv.y*nv.y;
                float n2v = zv.z + DT_C*pd2 + SQRT_DT_C*dv.z*nv.z;
                float n3v = zv.w + DT_C*pd3 + SQRT_DT_C*dv.w*nv.w;
                v8[j*4+0] = n0v; v8[j*4+1] = n1v; v8[j*4+2] = n2v; v8[j*4+3] = n3v;
                vmin = fminf(vmin, fminf(fminf(n0v, n1v), fminf(n2v, n3v)));
                vmax = fmaxf(vmax, fmaxf(fmaxf(n0v, n1v), fmaxf(n2v, n3v)));
            }
#pragma unroll
            for (int o = 16; o > 0; o >>= 1) {
                vmin = fminf(vmin, __shfl_xor_sync(0xffffffffu, vmin, o));
                vmax = fmaxf(vmax, __shfl_xor_sync(0xffffffffu, vmax, o));
            }
            const float inv = 1.f / (vmax - vmin);
#pragma unroll
            for (int j = 0; j < 2; j++) {
                const int cb = lane*4 + 128*j;
                *(float4*)&outz[cb] = make_float4((v8[j*4+0]-vmin)*inv, (v8[j*4+1]-vmin)*inv,
                                                  (v8[j*4+2]-vmin)*inv, (v8[j*4+3]-vmin)*inv);
            }
        }
        gridbar(tgt);
    }
}

// ---------------- small kernels ----------------
__global__ void reset_kernel()
{
    if (threadIdx.x < 32) g_cnt[threadIdx.x << 5] = 0u;
}

__global__ void mt_kernel(const float* __restrict__ M)
{
    int r = blockIdx.x * blockDim.x + threadIdx.x;
    if (r < TT * BB) {
        const float* p = M + (size_t)r * DD;
        float s = 0.f;
        for (int d = 0; d < DD; d++) s += p[d];
        g_Mt[r] = s * (1.f / DD);
    }
}

__global__ void z0_kernel(const float* __restrict__ cov,
                          const float* __restrict__ w1, const float* __restrict__ b1,
                          const float* __restrict__ w2, const float* __restrict__ b2)
{
    int b = blockIdx.x;
    __shared__ float cv[16];
    __shared__ float hid[64];
    if (threadIdx.x < 16) cv[threadIdx.x] = cov[b * 16 + threadIdx.x];
    __syncthreads();
    if (threadIdx.x < 64) {
        float s = b1[threadIdx.x];
        for (int i = 0; i < 16; i++) s += cv[i] * w1[i * 64 + threadIdx.x];
        hid[threadIdx.x] = fmaxf(s, 0.f);
    }
    __syncthreads();
    int n = threadIdx.x;
    float s = b2[n];
    for (int j = 0; j < 64; j++) s += hid[j] * w2[j * 256 + n];
    float z = tanhf(s);
    for (int ss = 0; ss < SS; ss++)
        g_states[(size_t)(b * SS + ss) * ZZ + n] = z;
}

__global__ void out_copy_kernel(float* __restrict__ out)
{
    int i = blockIdx.x * 256 + threadIdx.x;
    out[i] = g_states[(size_t)TT * BSZ * ZZ + i];
}

__global__ void scal_kernel(float* __restrict__ out)
{
    __shared__ float red[256];
    int tid = threadIdx.x;
    float s = 0.f;
    for (int i = tid; i < KLD_PARTS; i += 256) s += g_kld_part[i];
    red[tid] = s;
    __syncthreads();
    for (int o = 128; o > 0; o >>= 1) { if (tid < o) red[tid] += red[tid + o]; __syncthreads(); }
    float kldsum = red[0];
    __syncthreads();
    s = 0.f;
    for (int i = tid; i < RECON_PARTS; i += 256) s += g_recon_part[i];
    red[tid] = s;
    __syncthreads();
    for (int o = 128; o > 0; o >>= 1) { if (tid < o) red[tid] += red[tid + o]; __syncthreads(); }
    if (tid == 0) {
        float reconsum = red[0];
        float lk = (0.5f * DT_C / (float)(BB * SS)) * kldsum;
        float lr = reconsum * (1.f / (float)(BB * SS));
        out[131072] = lr + lk;   // loss_total
        out[131073] = lr;        // loss_recon
        out[131074] = lk;        // loss_kld
    }
}

// ---------------- launch ----------------
extern "C" void kernel_launch(void* const* d_in, const int* in_sizes, int n_in,
                              void* d_out, int out_size)
{
    (void)in_sizes; (void)n_in; (void)out_size;
    const float* X        = (const float*)d_in[0];
    const float* M        = (const float*)d_in[1];
    const float* cov      = (const float*)d_in[2];
    const float* path_h   = (const float*)d_in[3];
    const float* path_hpos= (const float*)d_in[4];
    const float* noise    = (const float*)d_in[5];
    const float* drift_w1 = (const float*)d_in[6];
    const float* drift_b1 = (const float*)d_in[7];
    const float* drift_w2 = (const float*)d_in[8];
    const float* drift_b2 = (const float*)d_in[9];
    const float* diff_w1  = (const float*)d_in[10];
    const float* diff_b1  = (const float*)d_in[11];
    const float* diff_w2  = (const float*)d_in[12];
    const float* diff_b2  = (const float*)d_in[13];
    const float* p_w1     = (const float*)d_in[14];
    const float* p_b1     = (const float*)d_in[15];
    const float* p_w2     = (const float*)d_in[16];
    const float* p_b2     = (const float*)d_in[17];
    const float* cov_w1   = (const float*)d_in[18];
    const float* cov_b1   = (const float*)d_in[19];
    const float* cov_w2   = (const float*)d_in[20];
    const float* cov_b2   = (const float*)d_in[21];
    float* out = (float*)d_out;

    float *hprior, *hpost, *ppart, *dtmp, *diffp, *states, *zw, *post, *A3, *kldp, *reconp, *Mtp;
    cudaGetSymbolAddress((void**)&hprior, g_hprior);
    cudaGetSymbolAddress((void**)&hpost,  g_hpost);
    cudaGetSymbolAddress((void**)&ppart,  g_ppart);
    cudaGetSymbolAddress((void**)&dtmp,   g_dtmp);
    cudaGetSymbolAddress((void**)&diffp,  g_diff);
    cudaGetSymbolAddress((void**)&states, g_states);
    cudaGetSymbolAddress((void**)&zw,     g_zw);
    cudaGetSymbolAddress((void**)&post,   g_post);
    cudaGetSymbolAddress((void**)&A3,     g_A3);
    cudaGetSymbolAddress((void**)&kldp,   g_kld_part);
    cudaGetSymbolAddress((void**)&reconp, g_recon_part);
    cudaGetSymbolAddress((void**)&Mtp,    g_Mt);

    static int smem_set = 0;
    if (!smem_set) {
        cudaFuncSetAttribute(scan_kernel,
                             cudaFuncAttributeMaxDynamicSharedMemorySize, SMEM_SCAN);
        smem_set = 1;
    }

    // ---- precompute (parallel over T) ----
    reset_kernel<<<1, 32>>>();
    gemm_t<PRO_PLAIN, EPI_STORE><<<dim3(16, 100), 256>>>(
        path_h, RR, drift_w1, HH, hprior, HH, RR, drift_b1,
        nullptr, nullptr, nullptr, nullptr);
    gemm_t<PRO_PLAIN, EPI_STORE><<<dim3(16, 100), 256>>>(
        path_hpos, RR, drift_w1, HH, hpost, HH, RR, drift_b1,
        nullptr, nullptr, nullptr, nullptr);
    gemm_t<PRO_PLAIN, EPI_STORE><<<dim3(16, 100), 256>>>(
        path_h, RR, p_w1, HH, ppart, HH, RR, p_b1,
        nullptr, nullptr, nullptr, nullptr);
    gemm_t<PRO_PLAIN, EPI_RELU><<<dim3(16, 100), 256>>>(
        path_h, RR, diff_w1, HH, dtmp, HH, RR, diff_b1,
        nullptr, nullptr, nullptr, nullptr);
    gemm_t<PRO_PLAIN, EPI_EXP><<<dim3(4, 100), 256>>>(
        dtmp, HH, diff_w2, ZZ, diffp, ZZ, HH, diff_b2,
        nullptr, nullptr, nullptr, nullptr);
    mt_kernel<<<(TT * BB + 255) / 256, 256>>>(M);
    z0_kernel<<<BB, 256>>>(cov, cov_w1, cov_b1, cov_w2, cov_b2);

    // ---- sequential scan: ONE persistent kernel for all 200 steps ----
    scan_kernel<<<SCAN_BLOCKS, SCAN_THREADS, SMEM_SCAN>>>(
        drift_w1 + (size_t)RR * HH, drift_w2, drift_b2, noise);

    // ---- batch epilogue (parallel over all T) ----
    gemm_t<PRO_ADDRELU, EPI_KLD><<<dim3(4, 800), 256>>>(
        zw, HH, drift_w2, ZZ, nullptr, 0, HH, drift_b2,
        hprior, post, diffp, kldp);
    gemm_t<PRO_PLAIN, EPI_BCASTRELU><<<dim3(16, 800), 256>>>(
        states + (size_t)BSZ * ZZ, ZZ, p_w1 + (size_t)RR * HH, HH,
        A3, HH, ZZ, nullptr, ppart, nullptr, nullptr, nullptr);
    gemm_t<PRO_PLAIN, EPI_RECON><<<dim3(2, 800), 256>>>(
        A3, HH, p_w2, DD, nullptr, 0, HH, p_b2,
        X, Mtp, nullptr, reconp);

    // ---- output: z_final then (total, recon, kld) ----
    out_copy_kernel<<<512, 256>>>(out);
    scal_kernel<<<1, 256>>>(out);
}

// round 10
// speedup vs baseline: 4.3274x; 1.0862x over previous
#include <cuda_runtime.h>
#include <math.h>
#include <stdint.h>

#define TT 200
#define BB 64
#define SS 8
#define DD 128
#define RR 512
#define ZZ 256
#define HH 1024
#define BSZ (BB*SS)            /* 512 rows per step */
#define DT_C 0.05f
#define SQRT_DT_C 0.223606797749979f
#define LOG2PI_C 1.8378770664093453f

#define KLD_PARTS  (800*4)
#define RECON_PARTS (800*2)

#define SCAN_BLOCKS 128
#define SCAN_THREADS 128

// ---------------- device scratch (static, allocation-free) ----------------
__device__ float g_hprior[TT*BB*HH];        // h@drift_w1[:R] + b1
__device__ float g_hpost [TT*BB*HH];        // hpos@drift_w1[:R] + b1
__device__ float g_ppart [TT*BB*HH];        // h@p_w1[:R] + p_b1
__device__ float g_dtmp  [TT*BB*HH];        // relu(h@diff_w1+b1)
__device__ float g_diff  [TT*BB*ZZ];        // exp(diff MLP)
__device__ float g_Mt    [TT*BB];
__device__ float g_states[(TT+1)*BSZ*ZZ];   // z trajectory (normalized)
__device__ float g_zw    [TT*BSZ*HH];       // z_t @ drift_w1[R:]
__device__ float g_post  [TT*BSZ*ZZ];       // posterior drift
__device__ float g_A3    [TT*BSZ*HH];       // decoder hidden
__device__ float g_part  [4*BSZ*ZZ];        // split-K partials for scan
__device__ float g_kld_part[KLD_PARTS];
__device__ float g_recon_part[RECON_PARTS];
__device__ unsigned g_cnt[32*32];           // spread barrier counters (128B apart)

// ---------------- tf32 / async helpers ----------------
__device__ __forceinline__ uint32_t f2tf(float f)
{
    uint32_t u;
    asm("cvt.rna.tf32.f32 %0, %1;" : "=r"(u) : "f"(f));
    return u;
}

__device__ __forceinline__ uint32_t f2tf_u(uint32_t raw)
{
    return f2tf(__uint_as_float(raw));
}

__device__ __forceinline__ void mma8(float* c,
    uint32_t a0, uint32_t a1, uint32_t a2, uint32_t a3,
    uint32_t b0, uint32_t b1)
{
    asm("mma.sync.aligned.m16n8k8.row.col.f32.tf32.tf32.f32 "
        "{%0,%1,%2,%3},{%4,%5,%6,%7},{%8,%9},{%0,%1,%2,%3};"
        : "+f"(c[0]), "+f"(c[1]), "+f"(c[2]), "+f"(c[3])
        : "r"(a0), "r"(a1), "r"(a2), "r"(a3), "r"(b0), "r"(b1));
}

__device__ __forceinline__ void cp16(uint32_t smem_dst, const void* gsrc)
{
    asm volatile("cp.async.cg.shared.global [%0], [%1], 16;\n"
                 :: "r"(smem_dst), "l"(gsrc));
}
#define CP_COMMIT() asm volatile("cp.async.commit_group;\n" ::: "memory")
#define CP_WAIT1()  asm volatile("cp.async.wait_group 1;\n" ::: "memory")
#define CP_WAIT0()  asm volatile("cp.async.wait_group 0;\n" ::: "memory")

// ---------------- generic 128x64 tf32 GEMM with fused pro/epilogues ------
// 256 threads, 8 warps in 4x2 grid, warp tile 32x32, k32 smem stages.
// PRO_PLAIN: cp.async double-buffered; fragments converted rna at consume.
// PRO_ADDRELU: synchronous staged (compute-at-stage) path.
#define PRO_PLAIN 0
#define PRO_ADDRELU 1      // A := relu(A + aux[(m>>3)*H + k])
#define EPI_STORE 0        // C = acc (+bias)
#define EPI_RELU  1
#define EPI_EXP   2
#define EPI_BCASTRELU 3    // C = relu(acc + aux[(m>>3)*H + n])
#define EPI_KLD   4        // reduce ((0.1 tanh(acc+b)-post)/diff)^2
#define EPI_RECON 5        // reduce 0.5(log2pi+(X-(acc+b))^2)*Mt

template<int PRO, int EPI>
__global__ void __launch_bounds__(256) gemm_t(
    const float* __restrict__ A, int lda,
    const float* __restrict__ Bm, int ldb,
    float* __restrict__ C, int ldc, int K,
    const float* __restrict__ bias,
    const float* __restrict__ aux,
    const float* __restrict__ aux2,
    const float* __restrict__ aux3,
    float* __restrict__ part)
{
    constexpr int AW = 36;            // A smem row stride (words), %32=4
    constexpr int BW = 72;            // B smem row stride (words), %32=8
    constexpr int ASZ = 128 * AW;
    constexpr int BSZW = 32 * BW;
    constexpr int NBUF = (PRO == PRO_PLAIN) ? 2 : 1;
    __shared__ uint32_t sm[NBUF * (ASZ + BSZW)];

    const int tid = threadIdx.x;
    const int m0 = blockIdx.y * 128, n0 = blockIdx.x * 64;
    const int wid = tid >> 5, lane = tid & 31;
    const int wm = (wid & 3) * 32;     // warp row offset (4 warps along m)
    const int wn = (wid >> 2) * 32;    // warp col offset (2 warps along n)
    const int qr = lane >> 2;          // 0..7
    const int qc = lane & 3;           // 0..3

    float acc[2][4][4];
#pragma unroll
    for (int h = 0; h < 2; h++)
#pragma unroll
        for (int j = 0; j < 4; j++)
#pragma unroll
            for (int c = 0; c < 4; c++) acc[h][j][c] = 0.f;

    if (PRO == PRO_PLAIN) {
        const uint32_t smb = (uint32_t)__cvta_generic_to_shared(sm);
        // stage chunk k0 into buffer b (async, raw fp32 bits)
        auto stage = [&](int k0, int b) {
#pragma unroll
            for (int i = 0; i < 4; i++) {            // A: 128 rows x 32 k
                int slot = tid + 256 * i;
                int row = slot >> 3, k4 = (slot & 7) << 2;
                cp16(smb + (uint32_t)(b * (ASZ + BSZW) + row * AW + k4) * 4,
                     &A[(size_t)(m0 + row) * lda + k0 + k4]);
            }
#pragma unroll
            for (int i = 0; i < 2; i++) {            // B: 32 rows x 64 n
                int slot = tid + 256 * i;
                int row = slot >> 4, n4 = (slot & 15) << 2;
                cp16(smb + (uint32_t)(b * (ASZ + BSZW) + ASZ + row * BW + n4) * 4,
                     &Bm[(size_t)(k0 + row) * ldb + n0 + n4]);
            }
            CP_COMMIT();
        };

        stage(0, 0);
        int buf = 0;
        for (int k0 = 0; k0 < K; k0 += 32) {
            if (k0 + 32 < K) stage(k0 + 32, buf ^ 1);
            if (k0 + 32 < K) { CP_WAIT1(); } else { CP_WAIT0(); }
            __syncthreads();
            const uint32_t* As = sm + buf * (ASZ + BSZW);
            const uint32_t* Bs = As + ASZ;
#pragma unroll
            for (int k8 = 0; k8 < 4; k8++) {
                const int kk = k8 * 8;
                // rna conversion at consume time (unbiased, matches R8 numerics)
                uint32_t a00 = f2tf_u(As[(wm + qr     ) * AW + kk + qc]);
                uint32_t a01 = f2tf_u(As[(wm + qr + 8 ) * AW + kk + qc]);
                uint32_t a02 = f2tf_u(As[(wm + qr     ) * AW + kk + qc + 4]);
                uint32_t a03 = f2tf_u(As[(wm + qr + 8 ) * AW + kk + qc + 4]);
                uint32_t a10 = f2tf_u(As[(wm + qr + 16) * AW + kk + qc]);
                uint32_t a11 = f2tf_u(As[(wm + qr + 24) * AW + kk + qc]);
                uint32_t a12 = f2tf_u(As[(wm + qr + 16) * AW + kk + qc + 4]);
                uint32_t a13 = f2tf_u(As[(wm + qr + 24) * AW + kk + qc + 4]);
#pragma unroll
                for (int j = 0; j < 4; j++) {
                    const int cn = wn + j * 8 + qr;
                    uint32_t b0 = f2tf_u(Bs[(kk + qc    ) * BW + cn]);
                    uint32_t b1 = f2tf_u(Bs[(kk + qc + 4) * BW + cn]);
                    mma8(acc[0][j], a00, a01, a02, a03, b0, b1);
                    mma8(acc[1][j], a10, a11, a12, a13, b0, b1);
                }
            }
            __syncthreads();
            buf ^= 1;
        }
    } else {
        // synchronous staged path (PRO_ADDRELU)
        uint32_t* As = sm;
        uint32_t* Bs = sm + ASZ;
        const int arow = tid >> 1;
        const int ab   = (tid & 1) * 16;
        const int brow = tid >> 3;
        const int bn   = (tid & 7) * 8;
        for (int k0 = 0; k0 < K; k0 += 32) {
#pragma unroll
            for (int i = 0; i < 4; i++) {
                float4 av = *(const float4*)&A[(size_t)(m0 + arow) * lda + k0 + ab + 4*i];
                const float4 hv = *(const float4*)&aux[(size_t)((m0 + arow) >> 3) * HH + k0 + ab + 4*i];
                av.x = fmaxf(av.x + hv.x, 0.f); av.y = fmaxf(av.y + hv.y, 0.f);
                av.z = fmaxf(av.z + hv.z, 0.f); av.w = fmaxf(av.w + hv.w, 0.f);
                uint4 t;
                t.x = f2tf(av.x); t.y = f2tf(av.y); t.z = f2tf(av.z); t.w = f2tf(av.w);
                *(uint4*)&As[arow * AW + ab + 4*i] = t;
            }
#pragma unroll
            for (int i = 0; i < 2; i++) {
                float4 bv = *(const float4*)&Bm[(size_t)(k0 + brow) * ldb + n0 + bn + 4*i];
                uint4 t;
                t.x = f2tf(bv.x); t.y = f2tf(bv.y); t.z = f2tf(bv.z); t.w = f2tf(bv.w);
                *(uint4*)&Bs[brow * BW + bn + 4*i] = t;
            }
            __syncthreads();
#pragma unroll
            for (int k8 = 0; k8 < 4; k8++) {
                const int kk = k8 * 8;
                uint32_t a00 = As[(wm + qr     ) * AW + kk + qc];
                uint32_t a01 = As[(wm + qr + 8 ) * AW + kk + qc];
                uint32_t a02 = As[(wm + qr     ) * AW + kk + qc + 4];
                uint32_t a03 = As[(wm + qr + 8 ) * AW + kk + qc + 4];
                uint32_t a10 = As[(wm + qr + 16) * AW + kk + qc];
                uint32_t a11 = As[(wm + qr + 24) * AW + kk + qc];
                uint32_t a12 = As[(wm + qr + 16) * AW + kk + qc + 4];
                uint32_t a13 = As[(wm + qr + 24) * AW + kk + qc + 4];
#pragma unroll
                for (int j = 0; j < 4; j++) {
                    const int cn = wn + j * 8 + qr;
                    uint32_t b0 = Bs[(kk + qc    ) * BW + cn];
                    uint32_t b1 = Bs[(kk + qc + 4) * BW + cn];
                    mma8(acc[0][j], a00, a01, a02, a03, b0, b1);
                    mma8(acc[1][j], a10, a11, a12, a13, b0, b1);
                }
            }
            __syncthreads();
        }
    }

    const int mA = m0 + wm + qr;
    const int nB0 = n0 + wn + qc * 2;

    if (EPI <= 3) {
        const bool hasb = (bias != nullptr);
#pragma unroll
        for (int h = 0; h < 2; h++) {
#pragma unroll
            for (int j = 0; j < 4; j++) {
                const int n = nB0 + j * 8;
                const int r0 = mA + h * 16, r1 = r0 + 8;
                float v[4] = {acc[h][j][0], acc[h][j][1], acc[h][j][2], acc[h][j][3]};
                const int mm[4] = {r0, r0, r1, r1};
                const int nn[4] = {n, n + 1, n, n + 1};
#pragma unroll
                for (int c = 0; c < 4; c++) {
                    if (hasb) v[c] += bias[nn[c]];
                    if (EPI == EPI_RELU) v[c] = fmaxf(v[c], 0.f);
                    if (EPI == EPI_EXP)  v[c] = expf(v[c]);
                    if (EPI == EPI_BCASTRELU)
                        v[c] = fmaxf(v[c] + aux[(size_t)(mm[c] >> 3) * HH + nn[c]], 0.f);
                }
                *(float2*)&C[(size_t)r0 * ldc + n] = make_float2(v[0], v[1]);
                *(float2*)&C[(size_t)r1 * ldc + n] = make_float2(v[2], v[3]);
            }
        }
    } else {
        float s = 0.f;
#pragma unroll
        for (int h = 0; h < 2; h++) {
#pragma unroll
            for (int j = 0; j < 4; j++) {
                const int n = nB0 + j * 8;
                const int r0 = mA + h * 16, r1 = r0 + 8;
                const int mm[4] = {r0, r0, r1, r1};
                const int nn[4] = {n, n + 1, n, n + 1};
#pragma unroll
                for (int c = 0; c < 4; c++) {
                    float v = acc[h][j][c] + bias[nn[c]];
                    if (EPI == EPI_KLD) {
                        float pr = 0.1f * tanhf(v);
                        float e = (pr - aux2[(size_t)mm[c] * ZZ + nn[c]]) /
                                  aux3[(size_t)(mm[c] >> 3) * ZZ + nn[c]];
                        s += e * e;
                    } else { // EPI_RECON
                        float d = aux[(size_t)(mm[c] >> 3) * DD + nn[c]] - v;
                        float nll = 0.5f * (LOG2PI_C + d * d);
                        s += nll * aux2[mm[c] >> 3];
                    }
                }
            }
        }
        __shared__ float red[256];
        red[tid] = s;
        __syncthreads();
        for (int o = 128; o > 0; o >>= 1) {
            if (tid < o) red[tid] += red[tid + o];
            __syncthreads();
        }
        if (tid == 0) part[blockIdx.y * gridDim.x + blockIdx.x] = red[0];
    }
}

// ---------------- persistent scan kernel (tf32, 4 warps, 32x32 tiles) -----
#define SMEM_SCAN ((256*72*2 + 64*260) * 4)

__device__ __forceinline__ void gridbar(unsigned& tgt)
{
    tgt += SCAN_BLOCKS;
    __syncthreads();
    if (threadIdx.x == 0) {
        __threadfence();
        atomicAdd(&g_cnt[(blockIdx.x & 31) << 5], 1u);
    }
    if (threadIdx.x < 32) {
        unsigned s;
        do {
            s = *(volatile unsigned*)&g_cnt[threadIdx.x << 5];
#pragma unroll
            for (int o = 16; o > 0; o >>= 1)
                s += __shfl_xor_sync(0xffffffffu, s, o);
        } while (s < tgt);
        __threadfence();
    }
    __syncthreads();
}

__global__ void __launch_bounds__(SCAN_THREADS, 1) scan_kernel(
    const float* __restrict__ w1z,      // drift_w1 + RR*HH
    const float* __restrict__ w2,       // drift_w2
    const float* __restrict__ b2,       // drift_b2
    const float* __restrict__ noise)
{
    extern __shared__ uint32_t smu[];
    uint32_t* W1s = smu;                     // [256][72]
    uint32_t* W2s = smu + 256*72;            // [256][72]
    uint32_t* St  = smu + 2*256*72;          // [64][260]

    const int tid = threadIdx.x;
    const int bid = blockIdx.x;
    const int wid = tid >> 5, lane = tid & 31;
    const int qr = lane >> 2;   // 0..7
    const int qc = lane & 3;    // 0..3

    const int bmA = bid >> 4;          // 0..7
    const int bnA = bid & 15;          // 0..15
    const int wmA = (wid & 1) * 32;
    const int wnA = (wid >> 1) * 32;

    const int kcB = bid & 3;
    const int moB = (bid >> 2) >> 2;
    const int noB = (bid >> 2) & 3;
    const int wrB = (wid & 1) * 32;
    const int wcB = (wid >> 1) * 32;

    for (int i = tid; i < 256*64; i += SCAN_THREADS) {
        int k = i >> 6, c = i & 63;
        W1s[k*72 + c] = f2tf(w1z[(size_t)k*HH + bnA*64 + c]);
        W2s[k*72 + c] = f2tf(w2[(size_t)(kcB*256 + k)*ZZ + noB*64 + c]);
    }
    __syncthreads();

    unsigned tgt = 0;

    for (int t = 0; t < TT; t++) {
        const float* z = g_states + (size_t)t*BSZ*ZZ;
        float* zwt = g_zw + (size_t)t*BSZ*HH;

        // ============ phase A: zw[t] = z_t @ w1z (tf32 mma) ============
        {
            for (int i = tid; i < 64*64; i += SCAN_THREADS) {
                int row = i >> 6, q = (i & 63) << 2;
                float4 f = *(const float4*)&z[(size_t)(bmA*64 + row)*ZZ + q];
                uint4 u;
                u.x = f2tf(f.x); u.y = f2tf(f.y); u.z = f2tf(f.z); u.w = f2tf(f.w);
                *(uint4*)&St[row*260 + q] = u;
            }
            __syncthreads();

            float acc[2][4][4];
#pragma unroll
            for (int h = 0; h < 2; h++)
#pragma unroll
                for (int j = 0; j < 4; j++)
#pragma unroll
                    for (int c = 0; c < 4; c++) acc[h][j][c] = 0.f;

#pragma unroll 4
            for (int kb = 0; kb < 32; kb++) {
                const int kk = kb * 8;
                uint32_t a00 = St[(wmA + qr     )*260 + kk + qc];
                uint32_t a01 = St[(wmA + qr + 8 )*260 + kk + qc];
                uint32_t a02 = St[(wmA + qr     )*260 + kk + qc + 4];
                uint32_t a03 = St[(wmA + qr + 8 )*260 + kk + qc + 4];
                uint32_t a10 = St[(wmA + qr + 16)*260 + kk + qc];
                uint32_t a11 = St[(wmA + qr + 24)*260 + kk + qc];
                uint32_t a12 = St[(wmA + qr + 16)*260 + kk + qc + 4];
                uint32_t a13 = St[(wmA + qr + 24)*260 + kk + qc + 4];
#pragma unroll
                for (int j = 0; j < 4; j++) {
                    const int n = wnA + j*8 + qr;
                    uint32_t b0 = W1s[(kk + qc    )*72 + n];
                    uint32_t b1 = W1s[(kk + qc + 4)*72 + n];
                    mma8(acc[0][j], a00, a01, a02, a03, b0, b1);
                    mma8(acc[1][j], a10, a11, a12, a13, b0, b1);
                }
            }
            const int mA = bmA*64 + wmA + qr;
#pragma unroll
            for (int h = 0; h < 2; h++) {
#pragma unroll
                for (int j = 0; j < 4; j++) {
                    const int n = bnA*64 + wnA + j*8 + qc*2;
                    const int r0 = mA + h*16;
                    *(float2*)&zwt[(size_t)r0*HH + n]     = make_float2(acc[h][j][0], acc[h][j][1]);
                    *(float2*)&zwt[(size_t)(r0+8)*HH + n] = make_float2(acc[h][j][2], acc[h][j][3]);
                }
            }
        }
        gridbar(tgt);

        // ============ phase B1: partial relu(zw+hpost)@W2 (tf32 mma) ============
        {
            const float* hp = g_hpost + (size_t)t*BB*HH;
            for (int i = tid; i < 64*64; i += SCAN_THREADS) {
                int row = i >> 6, q = (i & 63) << 2;
                int gk = kcB*256 + q;
                float4 f  = *(const float4*)&zwt[(size_t)(moB*64 + row)*HH + gk];
                float4 h4 = *(const float4*)&hp[(size_t)((moB*64 + row) >> 3)*HH + gk];
                uint4 u;
                u.x = f2tf(fmaxf(f.x + h4.x, 0.f));
                u.y = f2tf(fmaxf(f.y + h4.y, 0.f));
                u.z = f2tf(fmaxf(f.z + h4.z, 0.f));
                u.w = f2tf(fmaxf(f.w + h4.w, 0.f));
                *(uint4*)&St[row*260 + q] = u;
            }
            __syncthreads();

            float acc[2][4][4];
#pragma unroll
            for (int h = 0; h < 2; h++)
#pragma unroll
                for (int j = 0; j < 4; j++)
#pragma unroll
                    for (int c = 0; c < 4; c++) acc[h][j][c] = 0.f;

#pragma unroll 4
            for (int kb = 0; kb < 32; kb++) {
                const int kk = kb * 8;
                uint32_t a00 = St[(wrB + qr     )*260 + kk + qc];
                uint32_t a01 = St[(wrB + qr + 8 )*260 + kk + qc];
                uint32_t a02 = St[(wrB + qr     )*260 + kk + qc + 4];
                uint32_t a03 = St[(wrB + qr + 8 )*260 + kk + qc + 4];
                uint32_t a10 = St[(wrB + qr + 16)*260 + kk + qc];
                uint32_t a11 = St[(wrB + qr + 24)*260 + kk + qc];
                uint32_t a12 = St[(wrB + qr + 16)*260 + kk + qc + 4];
                uint32_t a13 = St[(wrB + qr + 24)*260 + kk + qc + 4];
#pragma unroll
                for (int j = 0; j < 4; j++) {
                    const int n = wcB + j*8 + qr;
                    uint32_t b0 = W2s[(kk + qc    )*72 + n];
                    uint32_t b1 = W2s[(kk + qc + 4)*72 + n];
                    mma8(acc[0][j], a00, a01, a02, a03, b0, b1);
                    mma8(acc[1][j], a10, a11, a12, a13, b0, b1);
                }
            }
            float* gp = g_part + (size_t)kcB*BSZ*ZZ;
            const int mB = moB*64 + wrB + qr;
#pragma unroll
            for (int h = 0; h < 2; h++) {
#pragma unroll
                for (int j = 0; j < 4; j++) {
                    const int n = noB*64 + wcB + j*8 + qc*2;
                    const int r0 = mB + h*16;
                    *(float2*)&gp[(size_t)r0*ZZ + n]     = make_float2(acc[h][j][0], acc[h][j][1]);
                    *(float2*)&gp[(size_t)(r0+8)*ZZ + n] = make_float2(acc[h][j][2], acc[h][j][3]);
                }
            }
        }
        gridbar(tgt);

        // ============ phase B2: combine + tanh + Euler + row minmax (fp32) ============
        {
            const int row = bid*4 + wid;
            const float* zr = g_states + (size_t)t*BSZ*ZZ + (size_t)row*ZZ;
            const float* nr = noise + (size_t)t*BSZ*ZZ + (size_t)row*ZZ;
            const float* dr = g_diff + ((size_t)t*BB + (row >> 3))*ZZ;
            float* pr = g_post + (size_t)t*BSZ*ZZ + (size_t)row*ZZ;
            float* outz = g_states + (size_t)(t+1)*BSZ*ZZ + (size_t)row*ZZ;

            float v8[8];
            float vmin = 3.4e38f, vmax = -3.4e38f;
#pragma unroll
            for (int j = 0; j < 2; j++) {
                const int cb = lane*4 + 128*j;
                float4 s  = *(const float4*)&g_part[0*BSZ*ZZ + (size_t)row*ZZ + cb];
                float4 s1 = *(const float4*)&g_part[1*BSZ*ZZ + (size_t)row*ZZ + cb];
                float4 s2 = *(const float4*)&g_part[2*BSZ*ZZ + (size_t)row*ZZ + cb];
                float4 s3 = *(const float4*)&g_part[3*BSZ*ZZ + (size_t)row*ZZ + cb];
                float4 bb = *(const float4*)&b2[cb];
                float4 zv = *(const float4*)&zr[cb];
                float4 nv = *(const float4*)&nr[cb];
                float4 dv = *(const float4*)&dr[cb];
                float pd0 = 0.1f * tanhf(s.x + s1.x + s2.x + s3.x + bb.x);
                float pd1 = 0.1f * tanhf(s.y + s1.y + s2.y + s3.y + bb.y);
                float pd2 = 0.1f * tanhf(s.z + s1.z + s2.z + s3.z + bb.z);
                float pd3 = 0.1f * tanhf(s.w + s1.w + s2.w + s3.w + bb.w);
                *(float4*)&pr[cb] = make_float4(pd0, pd1, pd2, pd3);
                float n0v = zv.x + DT_C*pd0 + SQRT_DT_C*dv.x*nv.x;
                float n1v = zv.y + DT_C*pd1 + SQRT_DT_C*dv.y*nv.y;
                float n2v = zv.z + DT_C*pd2 + SQRT_DT_C*dv.z*nv.z;
                float n3v = zv.w + DT_C*pd3 + SQRT_DT_C*dv.w*nv.w;
                v8[j*4+0] = n0v; v8[j*4+1] = n1v; v8[j*4+2] = n2v; v8[j*4+3] = n3v;
                vmin = fminf(vmin, fminf(fminf(n0v, n1v), fminf(n2v, n3v)));
                vmax = fmaxf(vmax, fmaxf(fmaxf(n0v, n1v), fmaxf(n2v, n3v)));
            }
#pragma unroll
            for (int o = 16; o > 0; o >>= 1) {
                vmin = fminf(vmin, __shfl_xor_sync(0xffffffffu, vmin, o));
                vmax = fmaxf(vmax, __shfl_xor_sync(0xffffffffu, vmax, o));
            }
            const float inv = 1.f / (vmax - vmin);
#pragma unroll
            for (int j = 0; j < 2; j++) {
                const int cb = lane*4 + 128*j;
                *(float4*)&outz[cb] = make_float4((v8[j*4+0]-vmin)*inv, (v8[j*4+1]-vmin)*inv,
                                                  (v8[j*4+2]-vmin)*inv, (v8[j*4+3]-vmin)*inv);
            }
        }
        gridbar(tgt);
    }
}

// ---------------- small kernels ----------------
__global__ void reset_kernel()
{
    if (threadIdx.x < 32) g_cnt[threadIdx.x << 5] = 0u;
}

__global__ void mt_kernel(const float* __restrict__ M)
{
    int r = blockIdx.x * blockDim.x + threadIdx.x;
    if (r < TT * BB) {
        const float* p = M + (size_t)r * DD;
        float s = 0.f;
        for (int d = 0; d < DD; d++) s += p[d];
        g_Mt[r] = s * (1.f / DD);
    }
}

__global__ void z0_kernel(const float* __restrict__ cov,
                          const float* __restrict__ w1, const float* __restrict__ b1,
                          const float* __restrict__ w2, const float* __restrict__ b2)
{
    int b = blockIdx.x;
    __shared__ float cv[16];
    __shared__ float hid[64];
    if (threadIdx.x < 16) cv[threadIdx.x] = cov[b * 16 + threadIdx.x];
    __syncthreads();
    if (threadIdx.x < 64) {
        float s = b1[threadIdx.x];
        for (int i = 0; i < 16; i++) s += cv[i] * w1[i * 64 + threadIdx.x];
        hid[threadIdx.x] = fmaxf(s, 0.f);
    }
    __syncthreads();
    int n = threadIdx.x;
    float s = b2[n];
    for (int j = 0; j < 64; j++) s += hid[j] * w2[j * 256 + n];
    float z = tanhf(s);
    for (int ss = 0; ss < SS; ss++)
        g_states[(size_t)(b * SS + ss) * ZZ + n] = z;
}

__global__ void out_copy_kernel(float* __restrict__ out)
{
    int i = blockIdx.x * 256 + threadIdx.x;
    out[i] = g_states[(size_t)TT * BSZ * ZZ + i];
}

__global__ void scal_kernel(float* __restrict__ out)
{
    __shared__ float red[256];
    int tid = threadIdx.x;
    float s = 0.f;
    for (int i = tid; i < KLD_PARTS; i += 256) s += g_kld_part[i];
    red[tid] = s;
    __syncthreads();
    for (int o = 128; o > 0; o >>= 1) { if (tid < o) red[tid] += red[tid + o]; __syncthreads(); }
    float kldsum = red[0];
    __syncthreads();
    s = 0.f;
    for (int i = tid; i < RECON_PARTS; i += 256) s += g_recon_part[i];
    red[tid] = s;
    __syncthreads();
    for (int o = 128; o > 0; o >>= 1) { if (tid < o) red[tid] += red[tid + o]; __syncthreads(); }
    if (tid == 0) {
        float reconsum = red[0];
        float lk = (0.5f * DT_C / (float)(BB * SS)) * kldsum;
        float lr = reconsum * (1.f / (float)(BB * SS));
        out[131072] = lr + lk;   // loss_total
        out[131073] = lr;        // loss_recon
        out[131074] = lk;        // loss_kld
    }
}

// ---------------- launch ----------------
extern "C" void kernel_launch(void* const* d_in, const int* in_sizes, int n_in,
                              void* d_out, int out_size)
{
    (void)in_sizes; (void)n_in; (void)out_size;
    const float* X        = (const float*)d_in[0];
    const float* M        = (const float*)d_in[1];
    const float* cov      = (const float*)d_in[2];
    const float* path_h   = (const float*)d_in[3];
    const float* path_hpos= (const float*)d_in[4];
    const float* noise    = (const float*)d_in[5];
    const float* drift_w1 = (const float*)d_in[6];
    const float* drift_b1 = (const float*)d_in[7];
    const float* drift_w2 = (const float*)d_in[8];
    const float* drift_b2 = (const float*)d_in[9];
    const float* diff_w1  = (const float*)d_in[10];
    const float* diff_b1  = (const float*)d_in[11];
    const float* diff_w2  = (const float*)d_in[12];
    const float* diff_b2  = (const float*)d_in[13];
    const float* p_w1     = (const float*)d_in[14];
    const float* p_b1     = (const float*)d_in[15];
    const float* p_w2     = (const float*)d_in[16];
    const float* p_b2     = (const float*)d_in[17];
    const float* cov_w1   = (const float*)d_in[18];
    const float* cov_b1   = (const float*)d_in[19];
    const float* cov_w2   = (const float*)d_in[20];
    const float* cov_b2   = (const float*)d_in[21];
    float* out = (float*)d_out;

    float *hprior, *hpost, *ppart, *dtmp, *diffp, *states, *zw, *post, *A3, *kldp, *reconp, *Mtp;
    cudaGetSymbolAddress((void**)&hprior, g_hprior);
    cudaGetSymbolAddress((void**)&hpost,  g_hpost);
    cudaGetSymbolAddress((void**)&ppart,  g_ppart);
    cudaGetSymbolAddress((void**)&dtmp,   g_dtmp);
    cudaGetSymbolAddress((void**)&diffp,  g_diff);
    cudaGetSymbolAddress((void**)&states, g_states);
    cudaGetSymbolAddress((void**)&zw,     g_zw);
    cudaGetSymbolAddress((void**)&post,   g_post);
    cudaGetSymbolAddress((void**)&A3,     g_A3);
    cudaGetSymbolAddress((void**)&kldp,   g_kld_part);
    cudaGetSymbolAddress((void**)&reconp, g_recon_part);
    cudaGetSymbolAddress((void**)&Mtp,    g_Mt);

    static int smem_set = 0;
    if (!smem_set) {
        cudaFuncSetAttribute(scan_kernel,
                             cudaFuncAttributeMaxDynamicSharedMemorySize, SMEM_SCAN);
        smem_set = 1;
    }

    // ---- precompute (parallel over T) ----
    reset_kernel<<<1, 32>>>();
    gemm_t<PRO_PLAIN, EPI_STORE><<<dim3(16, 100), 256>>>(
        path_h, RR, drift_w1, HH, hprior, HH, RR, drift_b1,
        nullptr, nullptr, nullptr, nullptr);
    gemm_t<PRO_PLAIN, EPI_STORE><<<dim3(16, 100), 256>>>(
        path_hpos, RR, drift_w1, HH, hpost, HH, RR, drift_b1,
        nullptr, nullptr, nullptr, nullptr);
    gemm_t<PRO_PLAIN, EPI_STORE><<<dim3(16, 100), 256>>>(
        path_h, RR, p_w1, HH, ppart, HH, RR, p_b1,
        nullptr, nullptr, nullptr, nullptr);
    gemm_t<PRO_PLAIN, EPI_RELU><<<dim3(16, 100), 256>>>(
        path_h, RR, diff_w1, HH, dtmp, HH, RR, diff_b1,
        nullptr, nullptr, nullptr, nullptr);
    gemm_t<PRO_PLAIN, EPI_EXP><<<dim3(4, 100), 256>>>(
        dtmp, HH, diff_w2, ZZ, diffp, ZZ, HH, diff_b2,
        nullptr, nullptr, nullptr, nullptr);
    mt_kernel<<<(TT * BB + 255) / 256, 256>>>(M);
    z0_kernel<<<BB, 256>>>(cov, cov_w1, cov_b1, cov_w2, cov_b2);

    // ---- sequential scan: ONE persistent kernel for all 200 steps ----
    scan_kernel<<<SCAN_BLOCKS, SCAN_THREADS, SMEM_SCAN>>>(
        drift_w1 + (size_t)RR * HH, drift_w2, drift_b2, noise);

    // ---- batch epilogue (parallel over all T) ----
    gemm_t<PRO_ADDRELU, EPI_KLD><<<dim3(4, 800), 256>>>(
        zw, HH, drift_w2, ZZ, nullptr, 0, HH, drift_b2,
        hprior, post, diffp, kldp);
    gemm_t<PRO_PLAIN, EPI_BCASTRELU><<<dim3(16, 800), 256>>>(
        states + (size_t)BSZ * ZZ, ZZ, p_w1 + (size_t)RR * HH, HH,
        A3, HH, ZZ, nullptr, ppart, nullptr, nullptr, nullptr);
    gemm_t<PRO_PLAIN, EPI_RECON><<<dim3(2, 800), 256>>>(
        A3, HH, p_w2, DD, nullptr, 0, HH, p_b2,
        X, Mtp, nullptr, reconp);

    // ---- output: z_final then (total, recon, kld) ----
    out_copy_kernel<<<512, 256>>>(out);
    scal_kernel<<<1, 256>>>(out);
}